// round 13
// baseline (speedup 1.0000x reference)
#include <cuda_runtime.h>
#include <cuda_fp16.h>
#include <math.h>
#include <stdint.h>

// Problem constants
#define PB 4
#define PN 2048
#define PF 256
#define PD 64      // NHID
#define PH 4       // NHEADS
#define PC 32      // NCLASS
#define PK1 256

// ---------------- scratch (device globals, no allocation) ----------------
__device__ float g_h2[PB * PN * PC];
__device__ float g_W2p[PH * PB * PN * PC];         // per-head gemm2 partials, 16 MB
__device__ uint32_t g_abits[PB * PN * (PN / 32)];  // adjacency bitmask
__device__ __half g_VtH[PB * PH * PD * PN];        // [g][d][n] fp16 (reused by layer 2)
__device__ __half g_e1p[PB * PH * PN];             // factored exps, fp16
__device__ __half g_e1m[PB * PH * PN];
__device__ __half g_e2p[PB * PH * PN];
__device__ __half g_e2m[PB * PH * PN];

// =========================== helpers ===================================
__device__ __forceinline__ uint32_t smem_u32(const void* p) {
    uint32_t a;
    asm("{ .reg .u64 t; cvta.to.shared.u64 t, %1; cvt.u32.u64 %0, t; }"
        : "=r"(a) : "l"(p));
    return a;
}
// pack2h(lo, hi): f16x2 with lo in bits[0:16)
__device__ __forceinline__ uint32_t pack2h(float lo, float hi) {
    uint32_t r;
    asm("cvt.rn.f16x2.f32 %0, %1, %2;" : "=r"(r) : "f"(hi), "f"(lo));
    return r;
}
// split pair into fp16 hi + fp16 residual (packed)
__device__ __forceinline__ void split2h(float x, float y, uint32_t& hi, uint32_t& lo) {
    hi = pack2h(x, y);
    __half2 hh = *(__half2*)&hi;
    lo = pack2h(x - __low2float(hh), y - __high2float(hh));
}
__device__ __forceinline__ void mma_f16(float* d, const uint32_t* a, const uint32_t* b) {
    asm volatile(
        "mma.sync.aligned.m16n8k16.row.col.f32.f16.f16.f32 "
        "{%0,%1,%2,%3}, {%4,%5,%6,%7}, {%8,%9}, {%0,%1,%2,%3};"
        : "+f"(d[0]), "+f"(d[1]), "+f"(d[2]), "+f"(d[3])
        : "r"(a[0]), "r"(a[1]), "r"(a[2]), "r"(a[3]), "r"(b[0]), "r"(b[1]));
}
__device__ __forceinline__ void ldsm_x4(uint32_t* r, uint32_t addr) {
    asm volatile("ldmatrix.sync.aligned.m8n8.x4.shared.b16 {%0,%1,%2,%3}, [%4];"
                 : "=r"(r[0]), "=r"(r[1]), "=r"(r[2]), "=r"(r[3]) : "r"(addr));
}
// 2-bit -> per-half mask32 (bits isolated FIRST — R9 lesson)
__device__ __forceinline__ uint32_t mask2(uint32_t w, int bb) {
    uint32_t y = (w >> bb) & 3u;
    return ((y | (y << 15)) & 0x00010001u) * 0xFFFFu;
}
// p = max(e1p*e2p, e1m*e2m) packed fp16x2 (== exp(leakyrelu(f1+f2)))
__device__ __forceinline__ uint32_t pmax2(__half2 e1p, __half2 e1m,
                                          uint32_t e2p, uint32_t e2m) {
    __half2 a = __hmul2(e1p, *(__half2*)&e2p);
    __half2 b = __hmul2(e1m, *(__half2*)&e2m);
    __half2 m = __hmax2(a, b);
    return *(uint32_t*)&m;
}
__device__ __forceinline__ float eluf(float v) {
    return v > 0.f ? v : expm1f(v);
}

// ---------------------------------------------------------------------------
// Kernel 1: Wh1 = x @ W[h] with FUSED epilogue (exps fp16 + transposed fp16 V)
// ---------------------------------------------------------------------------
__global__ void gemm1_kernel(const float* __restrict__ x,
                             const float* __restrict__ W,
                             const float* __restrict__ a1,
                             const float* __restrict__ a2,
                             __half* __restrict__ VtH,
                             __half* __restrict__ e1p, __half* __restrict__ e1m,
                             __half* __restrict__ e2p, __half* __restrict__ e2m)
{
    __shared__ __align__(16) float As[32][68];  // 8704 B (reused by epilogue)
    __shared__ __align__(16) float Bs[32][64];  // 8192 B

    const int it = blockIdx.x;
    const int bh = blockIdx.y;
    const int b  = bh >> 2;
    const int h  = bh & 3;
    const int i0 = it * 64;
    const int tid = threadIdx.x;
    const int tx = tid & 15, ty = tid >> 4;

    const float* A  = x + ((size_t)b * PN + i0) * PF;
    const float* Bw = W + (size_t)h * PF * PD;

    float acc[4][4];
#pragma unroll
    for (int u = 0; u < 4; u++)
#pragma unroll
        for (int v = 0; v < 4; v++) acc[u][v] = 0.f;

    for (int k0 = 0; k0 < PF; k0 += 32) {
        __syncthreads();
#pragma unroll
        for (int r = 0; r < 8; r++) {
            int e = tid + 256 * r;
            int row = e >> 5, col = e & 31;
            As[col][row] = A[(size_t)row * PF + k0 + col];
        }
#pragma unroll
        for (int r = 0; r < 8; r++) {
            int e = tid + 256 * r;
            int k = e >> 6, d = e & 63;
            Bs[k][d] = Bw[(size_t)(k0 + k) * PD + d];
        }
        __syncthreads();
#pragma unroll
        for (int k = 0; k < 32; k++) {
            float4 pa = *(const float4*)&As[k][ty * 4];
            float4 pb = *(const float4*)&Bs[k][tx * 4];
            acc[0][0] += pa.x * pb.x; acc[0][1] += pa.x * pb.y;
            acc[0][2] += pa.x * pb.z; acc[0][3] += pa.x * pb.w;
            acc[1][0] += pa.y * pb.x; acc[1][1] += pa.y * pb.y;
            acc[1][2] += pa.y * pb.z; acc[1][3] += pa.y * pb.w;
            acc[2][0] += pa.z * pb.x; acc[2][1] += pa.z * pb.y;
            acc[2][2] += pa.z * pb.z; acc[2][3] += pa.z * pb.w;
            acc[3][0] += pa.w * pb.x; acc[3][1] += pa.w * pb.y;
            acc[3][2] += pa.w * pb.z; acc[3][3] += pa.w * pb.w;
        }
    }

    // ---- epilogue stage 1: f1/f2 partials -> reduce -> exps ----
    const float4 A1 = *(const float4*)&a1[h * PD + tx * 4];
    const float4 A2 = *(const float4*)&a2[h * PD + tx * 4];
    __syncthreads();
    float* S1 = &As[0][0];   // [64][17]
    float* S2 = &Bs[0][0];   // [64][17]
#pragma unroll
    for (int u = 0; u < 4; u++) {
        int row = ty * 4 + u;
        S1[row * 17 + tx] = acc[u][0] * A1.x + acc[u][1] * A1.y
                          + acc[u][2] * A1.z + acc[u][3] * A1.w;
        S2[row * 17 + tx] = acc[u][0] * A2.x + acc[u][1] * A2.y
                          + acc[u][2] * A2.z + acc[u][3] * A2.w;
    }
    __syncthreads();
    if (tid < 64) {
        float f1 = 0.f, f2 = 0.f;
#pragma unroll
        for (int t = 0; t < 16; t++) { f1 += S1[tid * 17 + t]; f2 += S2[tid * 17 + t]; }
        size_t o = (size_t)bh * PN + i0 + tid;
        e1p[o] = __float2half(__expf(f1));
        e1m[o] = __float2half(__expf(0.2f * f1));
        e2p[o] = __float2half(__expf(f2));
        e2m[o] = __float2half(__expf(0.2f * f2));
    }
    __syncthreads();

    // ---- epilogue stage 2: transpose + fp16 -> VtH[bh][d][n] ----
    __half* T = (__half*)&As[0][0];   // [64][68] halves
#pragma unroll
    for (int v = 0; v < 4; v++) {
        uint2 tv;
        tv.x = pack2h(acc[0][v], acc[1][v]);
        tv.y = pack2h(acc[2][v], acc[3][v]);
        *(uint2*)&T[(tx * 4 + v) * 68 + ty * 4] = tv;
    }
    __syncthreads();
#pragma unroll
    for (int r = 0; r < 4; r++) {
        int e = tid + 256 * r;
        int d = e >> 4, q = e & 15;
        *(uint2*)(VtH + ((size_t)bh * PD + d) * PN + i0 + q * 4) =
            *(const uint2*)&T[d * 68 + q * 4];
    }
}

// ---------------------------------------------------------------------------
// Kernel 2: pack adj>0 into bitmask
// ---------------------------------------------------------------------------
__global__ void adjbits_kernel(const int* __restrict__ adj,
                               uint32_t* __restrict__ bits)
{
    size_t t = (size_t)blockIdx.x * 256 + threadIdx.x;
    int a = adj[t];
    unsigned m = __ballot_sync(0xffffffffu, a > 0);
    if ((threadIdx.x & 31) == 0) bits[t >> 5] = m;
}

// ---------------------------------------------------------------------------
// Kernel 3: warp-MMA attention. FUSE=true (layer 1) additionally computes the
//   per-head slice of  elu(h1) @ Wo  on tensor cores in the epilogue (3-term
//   fp16 split, ~1e-7 err) and writes per-head partials Wp — no h1 global.
//   FUSE=false (layer 2) writes the elu'd output tile to `out`.
// ---------------------------------------------------------------------------
template<int NC, bool FUSE>
__global__ void __launch_bounds__(256) attn_mma_kernel(
    const __half* __restrict__ e1pg, const __half* __restrict__ e1mg,
    const __half* __restrict__ e2pg, const __half* __restrict__ e2mg,
    const __half* __restrict__ Vt, const uint32_t* __restrict__ abits,
    const float* __restrict__ Wo, float* __restrict__ Wp,
    float* __restrict__ out, int hshift)
{
    __shared__ __align__(128) char Vs[NC * 128];   // [d][64 j] f16, SW128
    __shared__ uint2 es[32];                       // {e2p pair, e2m pair} per j-pair
    __shared__ uint32_t aws[128][2];
    __shared__ __align__(4) __half WoH_s[FUSE ? PD * PC : 2];  // [n][k], k contig
    __shared__ __align__(4) __half WoL_s[FUSE ? PD * PC : 2];

    const int tid = threadIdx.x;
    const int lane = tid & 31, wid = tid >> 5;
    const int g = blockIdx.y;
    const int b = g >> hshift;
    const int h = g & ((1 << hshift) - 1);
    const int i0 = blockIdx.x * 128;

    const int r0 = wid * 16 + (lane >> 2);   // tile row (0..127)
    const int r1 = r0 + 8;
    const int cq = (lane & 3) * 2;

    if constexpr (FUSE) {   // stage this head's Wo slice as fp16 hi/lo
        const float* Woh = Wo + (size_t)h * PD * PC;
        for (int e = tid; e < PD * PC; e += 256) {
            int k = e >> 5, n = e & 31;
            float v = Woh[k * PC + n];
            __half hv = __float2half_rn(v);
            WoH_s[n * PD + k] = hv;
            WoL_s[n * PD + k] = __float2half_rn(v - __half2float(hv));
        }
    }

    const __half2 E1p0 = __half2half2(e1pg[(size_t)g * PN + i0 + r0]);
    const __half2 E1m0 = __half2half2(e1mg[(size_t)g * PN + i0 + r0]);
    const __half2 E1p1 = __half2half2(e1pg[(size_t)g * PN + i0 + r1]);
    const __half2 E1m1 = __half2half2(e1mg[(size_t)g * PN + i0 + r1]);

    const uint32_t* pp = (const uint32_t*)(e2pg + (size_t)g * PN);
    const uint32_t* mm = (const uint32_t*)(e2mg + (size_t)g * PN);
    const __half* vbase = Vt + (size_t)g * NC * PN;
    const uint32_t* abase = abits + ((size_t)b * PN + i0) * (PN / 32);

    const uint32_t sVs = smem_u32(Vs);
    const int vrow_l = ((lane >> 4) << 3) + (lane & 7);
    const int vcol_l = ((lane >> 3) & 1) << 3;
    const uint32_t ONES2[2] = {0x3C003C00u, 0x3C003C00u};

    constexpr int VR = NC / 32;    // uint4 prefetch regs per thread
    uint4 vr[VR];
    uint2 er;
    uint32_t ar;

    // prefetch chunk 0
    {
#pragma unroll
        for (int r = 0; r < VR; r++) {
            int e = tid + 256 * r;
            int d = e >> 3, q = e & 7;
            vr[r] = *(const uint4*)(vbase + (size_t)d * PN + q * 8);
        }
        int l5 = tid & 31;
        er.x = pp[l5];
        er.y = mm[l5];
        ar = abase[(size_t)(tid >> 1) * (PN / 32) + (tid & 1)];
    }

    float acc[NC / 8][4];
#pragma unroll
    for (int nt = 0; nt < NC / 8; nt++)
#pragma unroll
        for (int u = 0; u < 4; u++) acc[nt][u] = 0.f;
    float accS[4] = {0.f, 0.f, 0.f, 0.f};

    for (int c = 0; c < 32; c++) {
        __syncthreads();                       // previous chunk's readers done
#pragma unroll
        for (int r = 0; r < VR; r++) {
            int e = tid + 256 * r;
            int d = e >> 3, q = e & 7;
            uint32_t off = d * 128 + q * 16;
            uint32_t sw = off ^ ((off >> 3) & 0x70);
            *(uint4*)(Vs + sw) = vr[r];
        }
        if (tid < 32) es[tid] = er;
        aws[tid >> 1][tid & 1] = ar;
        __syncthreads();                       // stage visible

        if (c + 1 < 32) {                      // prefetch next chunk
            const int j0n = (c + 1) * 64;
#pragma unroll
            for (int r = 0; r < VR; r++) {
                int e = tid + 256 * r;
                int d = e >> 3, q = e & 7;
                vr[r] = *(const uint4*)(vbase + (size_t)d * PN + j0n + q * 8);
            }
            int l5 = tid & 31;
            er.x = pp[j0n / 2 + l5];
            er.y = mm[j0n / 2 + l5];
            ar = abase[(size_t)(tid >> 1) * (PN / 32) + (j0n >> 5) + (tid & 1)];
        }

        const uint32_t aw00 = aws[r0][0], aw01 = aws[r0][1];
        const uint32_t aw10 = aws[r1][0], aw11 = aws[r1][1];

#pragma unroll
        for (int ks = 0; ks < 4; ks++) {
            const uint2 ea = es[ks * 8 + (lane & 3)];
            const uint2 eb = es[ks * 8 + (lane & 3) + 4];
            const uint32_t w0 = (ks < 2) ? aw00 : aw01;
            const uint32_t w1 = (ks < 2) ? aw10 : aw11;
            const int bb = (ks & 1) * 16 + cq;

            uint32_t a[4];
            a[0] = pmax2(E1p0, E1m0, ea.x, ea.y) & mask2(w0, bb);
            a[1] = pmax2(E1p1, E1m1, ea.x, ea.y) & mask2(w1, bb);
            a[2] = pmax2(E1p0, E1m0, eb.x, eb.y) & mask2(w0, bb + 8);
            a[3] = pmax2(E1p1, E1m1, eb.x, eb.y) & mask2(w1, bb + 8);

            mma_f16(accS, a, ONES2);           // row sums (exact fp32 accum)

#pragma unroll
            for (int np = 0; np < NC / 16; np++) {
                int vrow = np * 16 + vrow_l;
                int vcol = ks * 16 + vcol_l;
                uint32_t off = vrow * 128 + vcol * 2;
                off ^= (off >> 3) & 0x70;
                uint32_t bH[4];
                ldsm_x4(bH, sVs + off);
                mma_f16(acc[2 * np],     a, bH);
                mma_f16(acc[2 * np + 1], a, bH + 2);
            }
        }
    }

    float inv0 = accS[0] > 0.f ? 1.f / accS[0] : 0.f;
    float inv1 = accS[2] > 0.f ? 1.f / accS[2] : 0.f;

    // elu'd normalized tile, still in D-fragment layout (== A-fragment layout)
    float accE[NC / 8][4];
#pragma unroll
    for (int nt = 0; nt < NC / 8; nt++) {
        accE[nt][0] = eluf(acc[nt][0] * inv0);
        accE[nt][1] = eluf(acc[nt][1] * inv0);
        accE[nt][2] = eluf(acc[nt][2] * inv1);
        accE[nt][3] = eluf(acc[nt][3] * inv1);
    }

    if constexpr (FUSE) {
        // per-head partial: accE[128x64] @ Wo_h[64x32], 3-term fp16
        float accW[4][4];
#pragma unroll
        for (int nt = 0; nt < 4; nt++)
#pragma unroll
            for (int u = 0; u < 4; u++) accW[nt][u] = 0.f;

#pragma unroll
        for (int kt = 0; kt < 4; kt++) {
            uint32_t aH[4], aL[4];
            split2h(accE[2 * kt][0],     accE[2 * kt][1],     aH[0], aL[0]);
            split2h(accE[2 * kt][2],     accE[2 * kt][3],     aH[1], aL[1]);
            split2h(accE[2 * kt + 1][0], accE[2 * kt + 1][1], aH[2], aL[2]);
            split2h(accE[2 * kt + 1][2], accE[2 * kt + 1][3], aH[3], aL[3]);
            int k0 = kt * 16 + cq;
#pragma unroll
            for (int nt = 0; nt < 4; nt++) {
                int n = nt * 8 + (lane >> 2);
                uint32_t bH[2], bL[2];
                bH[0] = *(const uint32_t*)&WoH_s[n * PD + k0];
                bH[1] = *(const uint32_t*)&WoH_s[n * PD + k0 + 8];
                bL[0] = *(const uint32_t*)&WoL_s[n * PD + k0];
                bL[1] = *(const uint32_t*)&WoL_s[n * PD + k0 + 8];
                mma_f16(accW[nt], aH, bH);
                mma_f16(accW[nt], aH, bL);
                mma_f16(accW[nt], aL, bH);
            }
        }
        float* w0 = Wp + ((size_t)h * PB * PN + (size_t)b * PN + i0 + r0) * PC;
        float* w1 = Wp + ((size_t)h * PB * PN + (size_t)b * PN + i0 + r1) * PC;
#pragma unroll
        for (int nt = 0; nt < 4; nt++) {
            *(float2*)(w0 + nt * 8 + cq) = make_float2(accW[nt][0], accW[nt][1]);
            *(float2*)(w1 + nt * 8 + cq) = make_float2(accW[nt][2], accW[nt][3]);
        }
    } else {
        float* o0 = out + ((size_t)b * PN + i0 + r0) * PC;
        float* o1 = out + ((size_t)b * PN + i0 + r1) * PC;
#pragma unroll
        for (int nt = 0; nt < NC / 8; nt++) {
            int col = nt * 8 + cq;
            *(float2*)(o0 + col) = make_float2(accE[nt][0], accE[nt][1]);
            *(float2*)(o1 + col) = make_float2(accE[nt][2], accE[nt][3]);
        }
    }
}

// ---------------------------------------------------------------------------
// Kernel 4: combine per-head partials -> Wh2 row; ao1/ao2 dots -> exps (fp16);
//   transposed fp16 V write for layer 2. Warp per row.
// ---------------------------------------------------------------------------
__global__ void comb_kernel(const float* __restrict__ Wp,
                            const float* __restrict__ ao1,
                            const float* __restrict__ ao2,
                            __half* __restrict__ Vt2,
                            __half* __restrict__ e1p, __half* __restrict__ e1m,
                            __half* __restrict__ e2p, __half* __restrict__ e2m)
{
    int wrp = blockIdx.x * 8 + (threadIdx.x >> 5);   // row r in [0, PB*PN)
    int lane = threadIdx.x & 31;
    const size_t S = (size_t)PB * PN * PC;
    size_t o = (size_t)wrp * PC + lane;
    float v = Wp[o] + Wp[S + o] + Wp[2 * S + o] + Wp[3 * S + o];

    int b = wrp >> 11;
    int n = wrp & (PN - 1);
    Vt2[((size_t)b * PC + lane) * PN + n] = __float2half_rn(v);

    float s1 = v * ao1[lane], s2 = v * ao2[lane];
#pragma unroll
    for (int of = 16; of; of >>= 1) {
        s1 += __shfl_xor_sync(0xffffffffu, s1, of);
        s2 += __shfl_xor_sync(0xffffffffu, s2, of);
    }
    if (lane == 0) {
        e1p[wrp] = __float2half(__expf(s1));
        e1m[wrp] = __float2half(__expf(0.2f * s1));
        e2p[wrp] = __float2half(__expf(s2));
        e2m[wrp] = __float2half(__expf(0.2f * s2));
    }
}

// ---------------------------------------------------------------------------
// Kernel 5: gather + Linear(32,32) + PReLU + Linear(32,2)
// ---------------------------------------------------------------------------
__global__ void cls_kernel(const float* __restrict__ h2,
                           const int*   __restrict__ idcs,
                           const float* __restrict__ W1,
                           const float* __restrict__ b1,
                           const float* __restrict__ pw,
                           const float* __restrict__ W2,
                           const float* __restrict__ b2,
                           float* __restrict__ out)
{
    int wrp = blockIdx.x * (blockDim.x >> 5) + (threadIdx.x >> 5);
    int lane = threadIdx.x & 31;
    if (wrp >= PB * PK1) return;
    int b = wrp >> 8;
    int idx = idcs[wrp];
    const float* ef = h2 + ((size_t)b * PN + idx) * PC;

    float y = b1[lane];
#pragma unroll
    for (int d = 0; d < PC; d++) y += ef[d] * W1[d * PC + lane];
    y = y > 0.f ? y : pw[lane] * y;

    float o0 = y * W2[lane * 2 + 0];
    float o1 = y * W2[lane * 2 + 1];
#pragma unroll
    for (int o = 16; o; o >>= 1) {
        o0 += __shfl_xor_sync(0xffffffffu, o0, o);
        o1 += __shfl_xor_sync(0xffffffffu, o1, o);
    }
    if (lane == 0) {
        out[wrp * 2 + 0] = o0 + b2[0];
        out[wrp * 2 + 1] = o1 + b2[1];
    }
}

// ---------------------------------------------------------------------------
extern "C" void kernel_launch(void* const* d_in, const int* in_sizes, int n_in,
                              void* d_out, int out_size)
{
    const float* x    = (const float*)d_in[0];
    const int*   adj  = (const int*)  d_in[1];
    const int*   idcs = (const int*)  d_in[2];
    const float* W    = (const float*)d_in[3];
    const float* a1   = (const float*)d_in[4];
    const float* a2   = (const float*)d_in[5];
    const float* Wo   = (const float*)d_in[6];
    const float* ao1  = (const float*)d_in[7];
    const float* ao2  = (const float*)d_in[8];
    const float* W1   = (const float*)d_in[9];
    const float* b1   = (const float*)d_in[10];
    const float* pw   = (const float*)d_in[11];
    const float* W2   = (const float*)d_in[12];
    const float* b2   = (const float*)d_in[13];
    float* out = (float*)d_out;

    float *p_h2, *p_wp;
    __half *p_vh, *p_e1p, *p_e1m, *p_e2p, *p_e2m;
    uint32_t* p_ab;
    cudaGetSymbolAddress((void**)&p_h2,  g_h2);
    cudaGetSymbolAddress((void**)&p_wp,  g_W2p);
    cudaGetSymbolAddress((void**)&p_ab,  g_abits);
    cudaGetSymbolAddress((void**)&p_vh,  g_VtH);
    cudaGetSymbolAddress((void**)&p_e1p, g_e1p);
    cudaGetSymbolAddress((void**)&p_e1m, g_e1m);
    cudaGetSymbolAddress((void**)&p_e2p, g_e2p);
    cudaGetSymbolAddress((void**)&p_e2m, g_e2m);

    gemm1_kernel<<<dim3(PN / 64, PB * PH), 256>>>(x, W, a1, a2, p_vh,
                                                  p_e1p, p_e1m, p_e2p, p_e2m);
    adjbits_kernel<<<(PB * PN * PN) / 256, 256>>>(adj, p_ab);

    attn_mma_kernel<PD, true><<<dim3(PN / 128, PB * PH), 256>>>(
        p_e1p, p_e1m, p_e2p, p_e2m, p_vh, p_ab, Wo, p_wp, nullptr, 2);

    comb_kernel<<<PB * PN / 8, 256>>>(p_wp, ao1, ao2, p_vh,
                                      p_e1p, p_e1m, p_e2p, p_e2m);

    attn_mma_kernel<PC, false><<<dim3(PN / 128, PB), 256>>>(
        p_e1p, p_e1m, p_e2p, p_e2m, p_vh, p_ab, nullptr, nullptr, p_h2, 0);

    cls_kernel<<<(PB * PK1) / 8, 256>>>(p_h2, idcs, W1, b1, pw, W2, b2, out);
}

// round 14
// speedup vs baseline: 1.0514x; 1.0514x over previous
#include <cuda_runtime.h>
#include <cuda_fp16.h>
#include <math.h>
#include <stdint.h>

// Problem constants
#define PB 4
#define PN 2048
#define PF 256
#define PD 64      // NHID
#define PH 4       // NHEADS
#define PC 32      // NCLASS
#define PK1 256

// ---------------- scratch (device globals, no allocation) ----------------
__device__ float g_h2[PB * PN * PC];
__device__ __half g_W2p[PH * PB * PN * PC];        // per-head gemm2 partials, 8 MB
__device__ uint32_t g_abits[PB * PN * (PN / 32)];  // adjacency bitmask
__device__ __half g_VtH[PB * PH * PD * PN];        // [g][d][n] fp16 (reused by layer 2)
__device__ __half g_e1p[PB * PH * PN];             // factored exps, fp16
__device__ __half g_e1m[PB * PH * PN];
__device__ __half g_e2p[PB * PH * PN];
__device__ __half g_e2m[PB * PH * PN];

// =========================== helpers ===================================
__device__ __forceinline__ uint32_t smem_u32(const void* p) {
    uint32_t a;
    asm("{ .reg .u64 t; cvta.to.shared.u64 t, %1; cvt.u32.u64 %0, t; }"
        : "=r"(a) : "l"(p));
    return a;
}
// pack2h(lo, hi): f16x2 with lo in bits[0:16)
__device__ __forceinline__ uint32_t pack2h(float lo, float hi) {
    uint32_t r;
    asm("cvt.rn.f16x2.f32 %0, %1, %2;" : "=r"(r) : "f"(hi), "f"(lo));
    return r;
}
// split pair into fp16 hi + fp16 residual (packed)
__device__ __forceinline__ void split2h(float x, float y, uint32_t& hi, uint32_t& lo) {
    hi = pack2h(x, y);
    __half2 hh = *(__half2*)&hi;
    lo = pack2h(x - __low2float(hh), y - __high2float(hh));
}
__device__ __forceinline__ void mma_f16(float* d, const uint32_t* a, const uint32_t* b) {
    asm volatile(
        "mma.sync.aligned.m16n8k16.row.col.f32.f16.f16.f32 "
        "{%0,%1,%2,%3}, {%4,%5,%6,%7}, {%8,%9}, {%0,%1,%2,%3};"
        : "+f"(d[0]), "+f"(d[1]), "+f"(d[2]), "+f"(d[3])
        : "r"(a[0]), "r"(a[1]), "r"(a[2]), "r"(a[3]), "r"(b[0]), "r"(b[1]));
}
__device__ __forceinline__ void ldsm_x4(uint32_t* r, uint32_t addr) {
    asm volatile("ldmatrix.sync.aligned.m8n8.x4.shared.b16 {%0,%1,%2,%3}, [%4];"
                 : "=r"(r[0]), "=r"(r[1]), "=r"(r[2]), "=r"(r[3]) : "r"(addr));
}
// 2-bit -> per-half mask32 (bits isolated FIRST — R9 lesson)
__device__ __forceinline__ uint32_t mask2(uint32_t w, int bb) {
    uint32_t y = (w >> bb) & 3u;
    return ((y | (y << 15)) & 0x00010001u) * 0xFFFFu;
}
// p = max(e1p*e2p, e1m*e2m) packed fp16x2 (== exp(leakyrelu(f1+f2)))
__device__ __forceinline__ uint32_t pmax2(__half2 e1p, __half2 e1m,
                                          uint32_t e2p, uint32_t e2m) {
    __half2 a = __hmul2(e1p, *(__half2*)&e2p);
    __half2 b = __hmul2(e1m, *(__half2*)&e2m);
    __half2 m = __hmax2(a, b);
    return *(uint32_t*)&m;
}
__device__ __forceinline__ float eluf(float v) {
    return v > 0.f ? v : expm1f(v);
}

// ---------------------------------------------------------------------------
// Kernel 1: Wh1 = x @ W[h] with FUSED epilogue (exps fp16 + transposed fp16 V)
// ---------------------------------------------------------------------------
__global__ void gemm1_kernel(const float* __restrict__ x,
                             const float* __restrict__ W,
                             const float* __restrict__ a1,
                             const float* __restrict__ a2,
                             __half* __restrict__ VtH,
                             __half* __restrict__ e1p, __half* __restrict__ e1m,
                             __half* __restrict__ e2p, __half* __restrict__ e2m)
{
    __shared__ __align__(16) float As[32][68];  // 8704 B (reused by epilogue)
    __shared__ __align__(16) float Bs[32][64];  // 8192 B

    const int it = blockIdx.x;
    const int bh = blockIdx.y;
    const int b  = bh >> 2;
    const int h  = bh & 3;
    const int i0 = it * 64;
    const int tid = threadIdx.x;
    const int tx = tid & 15, ty = tid >> 4;

    const float* A  = x + ((size_t)b * PN + i0) * PF;
    const float* Bw = W + (size_t)h * PF * PD;

    float acc[4][4];
#pragma unroll
    for (int u = 0; u < 4; u++)
#pragma unroll
        for (int v = 0; v < 4; v++) acc[u][v] = 0.f;

    for (int k0 = 0; k0 < PF; k0 += 32) {
        __syncthreads();
#pragma unroll
        for (int r = 0; r < 8; r++) {
            int e = tid + 256 * r;
            int row = e >> 5, col = e & 31;
            As[col][row] = A[(size_t)row * PF + k0 + col];
        }
#pragma unroll
        for (int r = 0; r < 8; r++) {
            int e = tid + 256 * r;
            int k = e >> 6, d = e & 63;
            Bs[k][d] = Bw[(size_t)(k0 + k) * PD + d];
        }
        __syncthreads();
#pragma unroll
        for (int k = 0; k < 32; k++) {
            float4 pa = *(const float4*)&As[k][ty * 4];
            float4 pb = *(const float4*)&Bs[k][tx * 4];
            acc[0][0] += pa.x * pb.x; acc[0][1] += pa.x * pb.y;
            acc[0][2] += pa.x * pb.z; acc[0][3] += pa.x * pb.w;
            acc[1][0] += pa.y * pb.x; acc[1][1] += pa.y * pb.y;
            acc[1][2] += pa.y * pb.z; acc[1][3] += pa.y * pb.w;
            acc[2][0] += pa.z * pb.x; acc[2][1] += pa.z * pb.y;
            acc[2][2] += pa.z * pb.z; acc[2][3] += pa.z * pb.w;
            acc[3][0] += pa.w * pb.x; acc[3][1] += pa.w * pb.y;
            acc[3][2] += pa.w * pb.z; acc[3][3] += pa.w * pb.w;
        }
    }

    // ---- epilogue stage 1: f1/f2 partials -> reduce -> exps ----
    const float4 A1 = *(const float4*)&a1[h * PD + tx * 4];
    const float4 A2 = *(const float4*)&a2[h * PD + tx * 4];
    __syncthreads();
    float* S1 = &As[0][0];   // [64][17]
    float* S2 = &Bs[0][0];   // [64][17]
#pragma unroll
    for (int u = 0; u < 4; u++) {
        int row = ty * 4 + u;
        S1[row * 17 + tx] = acc[u][0] * A1.x + acc[u][1] * A1.y
                          + acc[u][2] * A1.z + acc[u][3] * A1.w;
        S2[row * 17 + tx] = acc[u][0] * A2.x + acc[u][1] * A2.y
                          + acc[u][2] * A2.z + acc[u][3] * A2.w;
    }
    __syncthreads();
    if (tid < 64) {
        float f1 = 0.f, f2 = 0.f;
#pragma unroll
        for (int t = 0; t < 16; t++) { f1 += S1[tid * 17 + t]; f2 += S2[tid * 17 + t]; }
        size_t o = (size_t)bh * PN + i0 + tid;
        e1p[o] = __float2half(__expf(f1));
        e1m[o] = __float2half(__expf(0.2f * f1));
        e2p[o] = __float2half(__expf(f2));
        e2m[o] = __float2half(__expf(0.2f * f2));
    }
    __syncthreads();

    // ---- epilogue stage 2: transpose + fp16 -> VtH[bh][d][n] ----
    __half* T = (__half*)&As[0][0];   // [64][68] halves
#pragma unroll
    for (int v = 0; v < 4; v++) {
        uint2 tv;
        tv.x = pack2h(acc[0][v], acc[1][v]);
        tv.y = pack2h(acc[2][v], acc[3][v]);
        *(uint2*)&T[(tx * 4 + v) * 68 + ty * 4] = tv;
    }
    __syncthreads();
#pragma unroll
    for (int r = 0; r < 4; r++) {
        int e = tid + 256 * r;
        int d = e >> 4, q = e & 15;
        *(uint2*)(VtH + ((size_t)bh * PD + d) * PN + i0 + q * 4) =
            *(const uint2*)&T[d * 68 + q * 4];
    }
}

// ---------------------------------------------------------------------------
// Kernel 2: pack adj>0 into bitmask
// ---------------------------------------------------------------------------
__global__ void adjbits_kernel(const int* __restrict__ adj,
                               uint32_t* __restrict__ bits)
{
    size_t t = (size_t)blockIdx.x * 256 + threadIdx.x;
    int a = adj[t];
    unsigned m = __ballot_sync(0xffffffffu, a > 0);
    if ((threadIdx.x & 31) == 0) bits[t >> 5] = m;
}

// ---------------------------------------------------------------------------
// Kernel 3: warp-MMA attention, DOUBLE-BUFFERED (1 sync/chunk), rowsum via
//   HADD2 accumulation (no rowsum MMA — frees legacy tensor pipe).
//   FUSE=true: epilogue computes per-head slice of elu(h1)@Wo on tensor cores
//   and writes fp16 partials Wp. FUSE=false: writes elu'd tile to out.
// ---------------------------------------------------------------------------
template<int NC, bool FUSE>
__global__ void __launch_bounds__(256) attn_mma_kernel(
    const __half* __restrict__ e1pg, const __half* __restrict__ e1mg,
    const __half* __restrict__ e2pg, const __half* __restrict__ e2mg,
    const __half* __restrict__ Vt, const uint32_t* __restrict__ abits,
    const float* __restrict__ Wo, __half* __restrict__ Wp,
    float* __restrict__ out, int hshift)
{
    __shared__ __align__(128) char Vs[2][NC * 128];   // double-buffered V tiles
    __shared__ uint2 es[2][32];
    __shared__ uint32_t aws[2][128][2];
    __shared__ __align__(4) __half WoH_s[FUSE ? PD * PC : 2];  // [n][k]
    __shared__ __align__(4) __half WoL_s[FUSE ? PD * PC : 2];

    const int tid = threadIdx.x;
    const int lane = tid & 31, wid = tid >> 5;
    const int g = blockIdx.y;
    const int b = g >> hshift;
    const int h = g & ((1 << hshift) - 1);
    const int i0 = blockIdx.x * 128;

    const int r0 = wid * 16 + (lane >> 2);   // tile row (0..127)
    const int r1 = r0 + 8;
    const int cq = (lane & 3) * 2;

    if constexpr (FUSE) {   // stage this head's Wo slice as fp16 hi/lo
        const float* Woh = Wo + (size_t)h * PD * PC;
        for (int e = tid; e < PD * PC; e += 256) {
            int k = e >> 5, n = e & 31;
            float v = Woh[k * PC + n];
            __half hv = __float2half_rn(v);
            WoH_s[n * PD + k] = hv;
            WoL_s[n * PD + k] = __float2half_rn(v - __half2float(hv));
        }
    }

    const __half2 E1p0 = __half2half2(e1pg[(size_t)g * PN + i0 + r0]);
    const __half2 E1m0 = __half2half2(e1mg[(size_t)g * PN + i0 + r0]);
    const __half2 E1p1 = __half2half2(e1pg[(size_t)g * PN + i0 + r1]);
    const __half2 E1m1 = __half2half2(e1mg[(size_t)g * PN + i0 + r1]);

    const uint32_t* pp = (const uint32_t*)(e2pg + (size_t)g * PN);
    const uint32_t* mm = (const uint32_t*)(e2mg + (size_t)g * PN);
    const __half* vbase = Vt + (size_t)g * NC * PN;
    const uint32_t* abase = abits + ((size_t)b * PN + i0) * (PN / 32);

    const int vrow_l = ((lane >> 4) << 3) + (lane & 7);
    const int vcol_l = ((lane >> 3) & 1) << 3;

    constexpr int VR = NC / 32;    // uint4 prefetch regs per thread
    uint4 vr[VR];
    uint2 er;
    uint32_t ar;
    const int l5 = tid & 31;
    const int pe = tid >> 3, pq = tid & 7;        // V prefetch element ids
    const size_t arow = (size_t)(tid >> 1) * (PN / 32) + (tid & 1);

#define PREFETCH_CHUNK(J0)                                                    \
    {                                                                         \
        _Pragma("unroll")                                                     \
        for (int r = 0; r < VR; r++) {                                        \
            int d = pe + 32 * r;                                              \
            vr[r] = *(const uint4*)(vbase + (size_t)d * PN + (J0) + pq * 8);  \
        }                                                                     \
        er.x = pp[(J0) / 2 + l5];                                             \
        er.y = mm[(J0) / 2 + l5];                                             \
        ar = abase[arow + ((J0) >> 5)];                                       \
    }

#define STORE_CHUNK(BUF)                                                      \
    {                                                                         \
        _Pragma("unroll")                                                     \
        for (int r = 0; r < VR; r++) {                                        \
            int d = pe + 32 * r;                                              \
            uint32_t off = d * 128 + pq * 16;                                 \
            uint32_t sw = off ^ ((off >> 3) & 0x70);                          \
            *(uint4*)(Vs[BUF] + sw) = vr[r];                                  \
        }                                                                     \
        if (tid < 32) es[BUF][tid] = er;                                      \
        aws[BUF][tid >> 1][tid & 1] = ar;                                     \
    }

    float acc[NC / 8][4];
#pragma unroll
    for (int nt = 0; nt < NC / 8; nt++)
#pragma unroll
        for (int u = 0; u < 4; u++) acc[nt][u] = 0.f;
    float rs0 = 0.f, rs1 = 0.f;

    PREFETCH_CHUNK(0);
    STORE_CHUNK(0);
    PREFETCH_CHUNK(64);
    __syncthreads();

    for (int c = 0; c < 32; c++) {
        const int buf = c & 1;
        if (c + 1 < 32) STORE_CHUNK(buf ^ 1);
        if (c + 2 < 32) PREFETCH_CHUNK((c + 2) * 64);

        const uint32_t sVs = smem_u32(Vs[buf]);
        const uint32_t aw00 = aws[buf][r0][0], aw01 = aws[buf][r0][1];
        const uint32_t aw10 = aws[buf][r1][0], aw11 = aws[buf][r1][1];

        __half2 h2s0 = __float2half2_rn(0.f);
        __half2 h2s1 = __float2half2_rn(0.f);

#pragma unroll
        for (int ks = 0; ks < 4; ks++) {
            const uint2 ea = es[buf][ks * 8 + (lane & 3)];
            const uint2 eb = es[buf][ks * 8 + (lane & 3) + 4];
            const uint32_t w0 = (ks < 2) ? aw00 : aw01;
            const uint32_t w1 = (ks < 2) ? aw10 : aw11;
            const int bb = (ks & 1) * 16 + cq;

            uint32_t a[4];
            a[0] = pmax2(E1p0, E1m0, ea.x, ea.y) & mask2(w0, bb);
            a[1] = pmax2(E1p1, E1m1, ea.x, ea.y) & mask2(w1, bb);
            a[2] = pmax2(E1p0, E1m0, eb.x, eb.y) & mask2(w0, bb + 8);
            a[3] = pmax2(E1p1, E1m1, eb.x, eb.y) & mask2(w1, bb + 8);

            // rowsum partials (fp16 pair adds, fp32-accumulated per chunk)
            h2s0 = __hadd2(h2s0, __hadd2(*(__half2*)&a[0], *(__half2*)&a[2]));
            h2s1 = __hadd2(h2s1, __hadd2(*(__half2*)&a[1], *(__half2*)&a[3]));

#pragma unroll
            for (int np = 0; np < NC / 16; np++) {
                int vrow = np * 16 + vrow_l;
                int vcol = ks * 16 + vcol_l;
                uint32_t off = vrow * 128 + vcol * 2;
                off ^= (off >> 3) & 0x70;
                uint32_t bH[4];
                ldsm_x4(bH, sVs + off);
                mma_f16(acc[2 * np],     a, bH);
                mma_f16(acc[2 * np + 1], a, bH + 2);
            }
        }
        {
            float2 f0 = __half22float2(h2s0);
            float2 f1 = __half22float2(h2s1);
            rs0 += f0.x + f0.y;
            rs1 += f1.x + f1.y;
        }
        __syncthreads();
    }
#undef PREFETCH_CHUNK
#undef STORE_CHUNK

    // reduce row sums across the 4 lanes sharing each row
    rs0 += __shfl_xor_sync(0xffffffffu, rs0, 1);
    rs0 += __shfl_xor_sync(0xffffffffu, rs0, 2);
    rs1 += __shfl_xor_sync(0xffffffffu, rs1, 1);
    rs1 += __shfl_xor_sync(0xffffffffu, rs1, 2);
    float inv0 = rs0 > 0.f ? 1.f / rs0 : 0.f;
    float inv1 = rs1 > 0.f ? 1.f / rs1 : 0.f;

    // elu'd normalized tile, D-fragment layout (== A-fragment layout)
    float accE[NC / 8][4];
#pragma unroll
    for (int nt = 0; nt < NC / 8; nt++) {
        accE[nt][0] = eluf(acc[nt][0] * inv0);
        accE[nt][1] = eluf(acc[nt][1] * inv0);
        accE[nt][2] = eluf(acc[nt][2] * inv1);
        accE[nt][3] = eluf(acc[nt][3] * inv1);
    }

    if constexpr (FUSE) {
        // per-head partial: accE[128x64] @ Wo_h[64x32], 3-term fp16
        float accW[4][4];
#pragma unroll
        for (int nt = 0; nt < 4; nt++)
#pragma unroll
            for (int u = 0; u < 4; u++) accW[nt][u] = 0.f;

#pragma unroll
        for (int kt = 0; kt < 4; kt++) {
            uint32_t aH[4], aL[4];
            split2h(accE[2 * kt][0],     accE[2 * kt][1],     aH[0], aL[0]);
            split2h(accE[2 * kt][2],     accE[2 * kt][3],     aH[1], aL[1]);
            split2h(accE[2 * kt + 1][0], accE[2 * kt + 1][1], aH[2], aL[2]);
            split2h(accE[2 * kt + 1][2], accE[2 * kt + 1][3], aH[3], aL[3]);
            int k0 = kt * 16 + cq;
#pragma unroll
            for (int nt = 0; nt < 4; nt++) {
                int n = nt * 8 + (lane >> 2);
                uint32_t bH[2], bL[2];
                bH[0] = *(const uint32_t*)&WoH_s[n * PD + k0];
                bH[1] = *(const uint32_t*)&WoH_s[n * PD + k0 + 8];
                bL[0] = *(const uint32_t*)&WoL_s[n * PD + k0];
                bL[1] = *(const uint32_t*)&WoL_s[n * PD + k0 + 8];
                mma_f16(accW[nt], aH, bH);
                mma_f16(accW[nt], aH, bL);
                mma_f16(accW[nt], aL, bH);
            }
        }
        __half* w0 = Wp + ((size_t)h * PB * PN + (size_t)b * PN + i0 + r0) * PC;
        __half* w1 = Wp + ((size_t)h * PB * PN + (size_t)b * PN + i0 + r1) * PC;
#pragma unroll
        for (int nt = 0; nt < 4; nt++) {
            *(uint32_t*)(w0 + nt * 8 + cq) = pack2h(accW[nt][0], accW[nt][1]);
            *(uint32_t*)(w1 + nt * 8 + cq) = pack2h(accW[nt][2], accW[nt][3]);
        }
    } else {
        float* o0 = out + ((size_t)b * PN + i0 + r0) * PC;
        float* o1 = out + ((size_t)b * PN + i0 + r1) * PC;
#pragma unroll
        for (int nt = 0; nt < NC / 8; nt++) {
            int col = nt * 8 + cq;
            *(float2*)(o0 + col) = make_float2(accE[nt][0], accE[nt][1]);
            *(float2*)(o1 + col) = make_float2(accE[nt][2], accE[nt][3]);
        }
    }
}

// ---------------------------------------------------------------------------
// Kernel 4: combine fp16 per-head partials -> Wh2 row; ao1/ao2 dots -> exps;
//   transposed fp16 V write for layer 2. Warp per row.
// ---------------------------------------------------------------------------
__global__ void comb_kernel(const __half* __restrict__ Wp,
                            const float* __restrict__ ao1,
                            const float* __restrict__ ao2,
                            __half* __restrict__ Vt2,
                            __half* __restrict__ e1p, __half* __restrict__ e1m,
                            __half* __restrict__ e2p, __half* __restrict__ e2m)
{
    int wrp = blockIdx.x * 8 + (threadIdx.x >> 5);   // row r in [0, PB*PN)
    int lane = threadIdx.x & 31;
    const size_t S = (size_t)PB * PN * PC;
    size_t o = (size_t)wrp * PC + lane;
    float v = __half2float(Wp[o]) + __half2float(Wp[S + o])
            + __half2float(Wp[2 * S + o]) + __half2float(Wp[3 * S + o]);

    int b = wrp >> 11;
    int n = wrp & (PN - 1);
    Vt2[((size_t)b * PC + lane) * PN + n] = __float2half_rn(v);

    float s1 = v * ao1[lane], s2 = v * ao2[lane];
#pragma unroll
    for (int of = 16; of; of >>= 1) {
        s1 += __shfl_xor_sync(0xffffffffu, s1, of);
        s2 += __shfl_xor_sync(0xffffffffu, s2, of);
    }
    if (lane == 0) {
        e1p[wrp] = __float2half(__expf(s1));
        e1m[wrp] = __float2half(__expf(0.2f * s1));
        e2p[wrp] = __float2half(__expf(s2));
        e2m[wrp] = __float2half(__expf(0.2f * s2));
    }
}

// ---------------------------------------------------------------------------
// Kernel 5: gather + Linear(32,32) + PReLU + Linear(32,2)
// ---------------------------------------------------------------------------
__global__ void cls_kernel(const float* __restrict__ h2,
                           const int*   __restrict__ idcs,
                           const float* __restrict__ W1,
                           const float* __restrict__ b1,
                           const float* __restrict__ pw,
                           const float* __restrict__ W2,
                           const float* __restrict__ b2,
                           float* __restrict__ out)
{
    int wrp = blockIdx.x * (blockDim.x >> 5) + (threadIdx.x >> 5);
    int lane = threadIdx.x & 31;
    if (wrp >= PB * PK1) return;
    int b = wrp >> 8;
    int idx = idcs[wrp];
    const float* ef = h2 + ((size_t)b * PN + idx) * PC;

    float y = b1[lane];
#pragma unroll
    for (int d = 0; d < PC; d++) y += ef[d] * W1[d * PC + lane];
    y = y > 0.f ? y : pw[lane] * y;

    float o0 = y * W2[lane * 2 + 0];
    float o1 = y * W2[lane * 2 + 1];
#pragma unroll
    for (int o = 16; o; o >>= 1) {
        o0 += __shfl_xor_sync(0xffffffffu, o0, o);
        o1 += __shfl_xor_sync(0xffffffffu, o1, o);
    }
    if (lane == 0) {
        out[wrp * 2 + 0] = o0 + b2[0];
        out[wrp * 2 + 1] = o1 + b2[1];
    }
}

// ---------------------------------------------------------------------------
extern "C" void kernel_launch(void* const* d_in, const int* in_sizes, int n_in,
                              void* d_out, int out_size)
{
    const float* x    = (const float*)d_in[0];
    const int*   adj  = (const int*)  d_in[1];
    const int*   idcs = (const int*)  d_in[2];
    const float* W    = (const float*)d_in[3];
    const float* a1   = (const float*)d_in[4];
    const float* a2   = (const float*)d_in[5];
    const float* Wo   = (const float*)d_in[6];
    const float* ao1  = (const float*)d_in[7];
    const float* ao2  = (const float*)d_in[8];
    const float* W1   = (const float*)d_in[9];
    const float* b1   = (const float*)d_in[10];
    const float* pw   = (const float*)d_in[11];
    const float* W2   = (const float*)d_in[12];
    const float* b2   = (const float*)d_in[13];
    float* out = (float*)d_out;

    float* p_h2;
    __half *p_wp, *p_vh, *p_e1p, *p_e1m, *p_e2p, *p_e2m;
    uint32_t* p_ab;
    cudaGetSymbolAddress((void**)&p_h2,  g_h2);
    cudaGetSymbolAddress((void**)&p_wp,  g_W2p);
    cudaGetSymbolAddress((void**)&p_ab,  g_abits);
    cudaGetSymbolAddress((void**)&p_vh,  g_VtH);
    cudaGetSymbolAddress((void**)&p_e1p, g_e1p);
    cudaGetSymbolAddress((void**)&p_e1m, g_e1m);
    cudaGetSymbolAddress((void**)&p_e2p, g_e2p);
    cudaGetSymbolAddress((void**)&p_e2m, g_e2m);

    gemm1_kernel<<<dim3(PN / 64, PB * PH), 256>>>(x, W, a1, a2, p_vh,
                                                  p_e1p, p_e1m, p_e2p, p_e2m);
    adjbits_kernel<<<(PB * PN * PN) / 256, 256>>>(adj, p_ab);

    attn_mma_kernel<PD, true><<<dim3(PN / 128, PB * PH), 256>>>(
        p_e1p, p_e1m, p_e2p, p_e2m, p_vh, p_ab, Wo, p_wp, nullptr, 2);

    comb_kernel<<<PB * PN / 8, 256>>>(p_wp, ao1, ao2, p_vh,
                                      p_e1p, p_e1m, p_e2p, p_e2m);

    attn_mma_kernel<PC, false><<<dim3(PN / 128, PB), 256>>>(
        p_e1p, p_e1m, p_e2p, p_e2m, p_vh, p_ab, nullptr, nullptr, p_h2, 0);

    cls_kernel<<<(PB * PK1) / 8, 256>>>(p_h2, idcs, W1, b1, pw, W2, b2, out);
}

// round 15
// speedup vs baseline: 1.0911x; 1.0378x over previous
#include <cuda_runtime.h>
#include <cuda_fp16.h>
#include <math.h>
#include <stdint.h>

// Problem constants
#define PB 4
#define PN 2048
#define PF 256
#define PD 64      // NHID
#define PH 4       // NHEADS
#define PC 32      // NCLASS
#define PK1 256

// ---------------- scratch (device globals, no allocation) ----------------
__device__ float g_h2[PB * PN * PC];
__device__ __half g_W2p[PH * PB * PN * PC];        // per-head gemm2 partials, 8 MB
__device__ uint32_t g_abits[PB * PN * (PN / 32)];  // adjacency bitmask
__device__ __half g_VtH[PB * PH * PD * PN];        // [g][d][n] fp16 (reused by layer 2)
__device__ __half g_xH[PB * PN * PF];              // x split hi, 4 MB
__device__ __half g_xL[PB * PN * PF];              // x split lo, 4 MB
__device__ __half g_e1p[PB * PH * PN];             // factored exps, fp16
__device__ __half g_e1m[PB * PH * PN];
__device__ __half g_e2p[PB * PH * PN];
__device__ __half g_e2m[PB * PH * PN];

// =========================== helpers ===================================
__device__ __forceinline__ uint32_t smem_u32(const void* p) {
    uint32_t a;
    asm("{ .reg .u64 t; cvta.to.shared.u64 t, %1; cvt.u32.u64 %0, t; }"
        : "=r"(a) : "l"(p));
    return a;
}
// pack2h(lo, hi): f16x2 with lo in bits[0:16)
__device__ __forceinline__ uint32_t pack2h(float lo, float hi) {
    uint32_t r;
    asm("cvt.rn.f16x2.f32 %0, %1, %2;" : "=r"(r) : "f"(hi), "f"(lo));
    return r;
}
// split pair into fp16 hi + fp16 residual (packed)
__device__ __forceinline__ void split2h(float x, float y, uint32_t& hi, uint32_t& lo) {
    hi = pack2h(x, y);
    __half2 hh = *(__half2*)&hi;
    lo = pack2h(x - __low2float(hh), y - __high2float(hh));
}
__device__ __forceinline__ void mma_f16(float* d, const uint32_t* a, const uint32_t* b) {
    asm volatile(
        "mma.sync.aligned.m16n8k16.row.col.f32.f16.f16.f32 "
        "{%0,%1,%2,%3}, {%4,%5,%6,%7}, {%8,%9}, {%0,%1,%2,%3};"
        : "+f"(d[0]), "+f"(d[1]), "+f"(d[2]), "+f"(d[3])
        : "r"(a[0]), "r"(a[1]), "r"(a[2]), "r"(a[3]), "r"(b[0]), "r"(b[1]));
}
__device__ __forceinline__ void ldsm_x4(uint32_t* r, uint32_t addr) {
    asm volatile("ldmatrix.sync.aligned.m8n8.x4.shared.b16 {%0,%1,%2,%3}, [%4];"
                 : "=r"(r[0]), "=r"(r[1]), "=r"(r[2]), "=r"(r[3]) : "r"(addr));
}
// 2-bit -> per-half mask32 (bits isolated FIRST — R9 lesson)
__device__ __forceinline__ uint32_t mask2(uint32_t w, int bb) {
    uint32_t y = (w >> bb) & 3u;
    return ((y | (y << 15)) & 0x00010001u) * 0xFFFFu;
}
// p = max(e1p*e2p, e1m*e2m) packed fp16x2 (== exp(leakyrelu(f1+f2)))
__device__ __forceinline__ uint32_t pmax2(__half2 e1p, __half2 e1m,
                                          uint32_t e2p, uint32_t e2m) {
    __half2 a = __hmul2(e1p, *(__half2*)&e2p);
    __half2 b = __hmul2(e1m, *(__half2*)&e2m);
    __half2 m = __hmax2(a, b);
    return *(uint32_t*)&m;
}
__device__ __forceinline__ float eluf(float v) {
    return v > 0.f ? v : expm1f(v);
}

// ---------------------------------------------------------------------------
// Kernel 0: split x fp32 -> fp16 hi/lo
// ---------------------------------------------------------------------------
__global__ void xsplit_kernel(const float* __restrict__ x,
                              __half* __restrict__ xH, __half* __restrict__ xL)
{
    int t = (blockIdx.x * 256 + threadIdx.x) * 4;
    float4 v = *(const float4*)(x + t);
    uint32_t h0, l0, h1, l1;
    split2h(v.x, v.y, h0, l0);
    split2h(v.z, v.w, h1, l1);
    *(uint2*)(xH + t) = make_uint2(h0, h1);
    *(uint2*)(xL + t) = make_uint2(l0, l1);
}

// ---------------------------------------------------------------------------
// Kernel 1: tensor-core gemm1: Wh1 = x @ W[h]  (3-term fp16 split, ~1e-7 err)
//   128 rows per block, grid (PN/128, PB*PH). W_h staged in smem [d][f]
//   (stride 264 halves: conflict-free B-frag loads). A-frags direct from
//   global xH/xL. No syncthreads in mainloop. Fused epilogue: f1/f2 exps
//   (quad-shuffle) + transposed fp16 V via smem (overlaid on dead W region).
// SMEM: [0,33792) WsH | [33792,67584) WsL | [67584,68096) a1s/a2s
//       after mainloop: Ts[128][72] halves overlays [0,18432)
// ---------------------------------------------------------------------------
#define WS_STRIDE 264
#define SM1_TOTAL (67584 + 512)

__global__ void __launch_bounds__(256) gemm1_mma_kernel(
    const __half* __restrict__ xH, const __half* __restrict__ xL,
    const float* __restrict__ W,
    const float* __restrict__ a1, const float* __restrict__ a2,
    __half* __restrict__ VtH,
    __half* __restrict__ e1p, __half* __restrict__ e1m,
    __half* __restrict__ e2p, __half* __restrict__ e2m)
{
    extern __shared__ char sm1[];
    __half* WsH = (__half*)sm1;                    // [64][WS_STRIDE]
    __half* WsL = (__half*)(sm1 + 33792);
    float* a1s = (float*)(sm1 + 67584);            // [64]
    float* a2s = a1s + 64;

    const int it = blockIdx.x;
    const int bh = blockIdx.y;
    const int b  = bh >> 2;
    const int h  = bh & 3;
    const int i0 = it * 128;
    const int tid = threadIdx.x;
    const int lane = tid & 31, wid = tid >> 5;

    // stage W[h] (256x64, d contig) transposed into Ws[d][f], hi/lo split
    {
        const float* Wh = W + (size_t)h * PF * PD;
        for (int e = tid; e < PF * PD; e += 256) {
            int d = e & 63, f = e >> 6;
            float v = Wh[(size_t)f * PD + d];
            __half hv = __float2half_rn(v);
            WsH[d * WS_STRIDE + f] = hv;
            WsL[d * WS_STRIDE + f] = __float2half_rn(v - __half2float(hv));
        }
        if (tid < 64) { a1s[tid] = a1[h * PD + tid]; a2s[tid] = a2[h * PD + tid]; }
    }
    __syncthreads();

    const int r0 = wid * 16 + (lane >> 2);   // tile row
    const int r1 = r0 + 8;
    const int cq = (lane & 3) * 2;
    const __half* xr0H = xH + ((size_t)b * PN + i0 + r0) * PF;
    const __half* xr1H = xH + ((size_t)b * PN + i0 + r1) * PF;
    const __half* xr0L = xL + ((size_t)b * PN + i0 + r0) * PF;
    const __half* xr1L = xL + ((size_t)b * PN + i0 + r1) * PF;

    float acc[8][4];
#pragma unroll
    for (int nt = 0; nt < 8; nt++)
#pragma unroll
        for (int u = 0; u < 4; u++) acc[nt][u] = 0.f;

#pragma unroll 4
    for (int ks = 0; ks < 16; ks++) {
        const int k0 = ks * 16 + cq;
        uint32_t aH[4], aL[4];
        aH[0] = *(const uint32_t*)(xr0H + k0);
        aH[1] = *(const uint32_t*)(xr1H + k0);
        aH[2] = *(const uint32_t*)(xr0H + k0 + 8);
        aH[3] = *(const uint32_t*)(xr1H + k0 + 8);
        aL[0] = *(const uint32_t*)(xr0L + k0);
        aL[1] = *(const uint32_t*)(xr1L + k0);
        aL[2] = *(const uint32_t*)(xr0L + k0 + 8);
        aL[3] = *(const uint32_t*)(xr1L + k0 + 8);
#pragma unroll
        for (int nt = 0; nt < 8; nt++) {
            int n = nt * 8 + (lane >> 2);
            uint32_t bH[2], bL[2];
            bH[0] = *(const uint32_t*)&WsH[n * WS_STRIDE + k0];
            bH[1] = *(const uint32_t*)&WsH[n * WS_STRIDE + k0 + 8];
            bL[0] = *(const uint32_t*)&WsL[n * WS_STRIDE + k0];
            bL[1] = *(const uint32_t*)&WsL[n * WS_STRIDE + k0 + 8];
            mma_f16(acc[nt], aH, bH);
            mma_f16(acc[nt], aH, bL);
            mma_f16(acc[nt], aL, bH);
        }
    }

    // ---- f1/f2 dots via quad shuffles, then exps ----
    {
        float p10 = 0.f, p20 = 0.f, p11 = 0.f, p21 = 0.f;
#pragma unroll
        for (int nt = 0; nt < 8; nt++) {
            float w1a = a1s[nt * 8 + cq], w1b = a1s[nt * 8 + cq + 1];
            float w2a = a2s[nt * 8 + cq], w2b = a2s[nt * 8 + cq + 1];
            p10 += acc[nt][0] * w1a + acc[nt][1] * w1b;
            p20 += acc[nt][0] * w2a + acc[nt][1] * w2b;
            p11 += acc[nt][2] * w1a + acc[nt][3] * w1b;
            p21 += acc[nt][2] * w2a + acc[nt][3] * w2b;
        }
        p10 += __shfl_xor_sync(0xffffffffu, p10, 1);
        p10 += __shfl_xor_sync(0xffffffffu, p10, 2);
        p20 += __shfl_xor_sync(0xffffffffu, p20, 1);
        p20 += __shfl_xor_sync(0xffffffffu, p20, 2);
        p11 += __shfl_xor_sync(0xffffffffu, p11, 1);
        p11 += __shfl_xor_sync(0xffffffffu, p11, 2);
        p21 += __shfl_xor_sync(0xffffffffu, p21, 1);
        p21 += __shfl_xor_sync(0xffffffffu, p21, 2);
        if ((lane & 3) == 0) {
            size_t o0 = (size_t)bh * PN + i0 + r0;
            size_t o1 = (size_t)bh * PN + i0 + r1;
            e1p[o0] = __float2half(__expf(p10));
            e1m[o0] = __float2half(__expf(0.2f * p10));
            e2p[o0] = __float2half(__expf(p20));
            e2m[o0] = __float2half(__expf(0.2f * p20));
            e1p[o1] = __float2half(__expf(p11));
            e1m[o1] = __float2half(__expf(0.2f * p11));
            e2p[o1] = __float2half(__expf(p21));
            e2m[o1] = __float2half(__expf(0.2f * p21));
        }
    }

    // ---- transposed fp16 V via smem (overlay on Ws after all warps done) ----
    __syncthreads();
    __half* Ts = (__half*)sm1;   // [128][72]
#pragma unroll
    for (int nt = 0; nt < 8; nt++) {
        *(uint32_t*)&Ts[r0 * 72 + nt * 8 + cq] = pack2h(acc[nt][0], acc[nt][1]);
        *(uint32_t*)&Ts[r1 * 72 + nt * 8 + cq] = pack2h(acc[nt][2], acc[nt][3]);
    }
    __syncthreads();
    {
        int d = tid >> 2, ng = tid & 3;
        __half* dst = VtH + ((size_t)bh * PD + d) * PN + i0 + ng * 32;
#pragma unroll
        for (int m = 0; m < 8; m++) {
            int n = ng * 32 + m * 4;
            uint2 v;
            v.x = pack2h(__half2float(Ts[n * 72 + d]),
                         __half2float(Ts[(n + 1) * 72 + d]));
            v.y = pack2h(__half2float(Ts[(n + 2) * 72 + d]),
                         __half2float(Ts[(n + 3) * 72 + d]));
            *(uint2*)(dst + m * 4) = v;
        }
    }
}

// ---------------------------------------------------------------------------
// Kernel 2: pack adj>0 into bitmask
// ---------------------------------------------------------------------------
__global__ void adjbits_kernel(const int* __restrict__ adj,
                               uint32_t* __restrict__ bits)
{
    size_t t = (size_t)blockIdx.x * 256 + threadIdx.x;
    int a = adj[t];
    unsigned m = __ballot_sync(0xffffffffu, a > 0);
    if ((threadIdx.x & 31) == 0) bits[t >> 5] = m;
}

// ---------------------------------------------------------------------------
// Kernel 3: warp-MMA attention, double-buffered, HADD2 rowsums (R13, passing)
// ---------------------------------------------------------------------------
template<int NC, bool FUSE>
__global__ void __launch_bounds__(256) attn_mma_kernel(
    const __half* __restrict__ e1pg, const __half* __restrict__ e1mg,
    const __half* __restrict__ e2pg, const __half* __restrict__ e2mg,
    const __half* __restrict__ Vt, const uint32_t* __restrict__ abits,
    const float* __restrict__ Wo, __half* __restrict__ Wp,
    float* __restrict__ out, int hshift)
{
    __shared__ __align__(128) char Vs[2][NC * 128];
    __shared__ uint2 es[2][32];
    __shared__ uint32_t aws[2][128][2];
    __shared__ __align__(4) __half WoH_s[FUSE ? PD * PC : 2];
    __shared__ __align__(4) __half WoL_s[FUSE ? PD * PC : 2];

    const int tid = threadIdx.x;
    const int lane = tid & 31, wid = tid >> 5;
    const int g = blockIdx.y;
    const int b = g >> hshift;
    const int h = g & ((1 << hshift) - 1);
    const int i0 = blockIdx.x * 128;

    const int r0 = wid * 16 + (lane >> 2);
    const int r1 = r0 + 8;
    const int cq = (lane & 3) * 2;

    if constexpr (FUSE) {
        const float* Woh = Wo + (size_t)h * PD * PC;
        for (int e = tid; e < PD * PC; e += 256) {
            int k = e >> 5, n = e & 31;
            float v = Woh[k * PC + n];
            __half hv = __float2half_rn(v);
            WoH_s[n * PD + k] = hv;
            WoL_s[n * PD + k] = __float2half_rn(v - __half2float(hv));
        }
    }

    const __half2 E1p0 = __half2half2(e1pg[(size_t)g * PN + i0 + r0]);
    const __half2 E1m0 = __half2half2(e1mg[(size_t)g * PN + i0 + r0]);
    const __half2 E1p1 = __half2half2(e1pg[(size_t)g * PN + i0 + r1]);
    const __half2 E1m1 = __half2half2(e1mg[(size_t)g * PN + i0 + r1]);

    const uint32_t* pp = (const uint32_t*)(e2pg + (size_t)g * PN);
    const uint32_t* mm = (const uint32_t*)(e2mg + (size_t)g * PN);
    const __half* vbase = Vt + (size_t)g * NC * PN;
    const uint32_t* abase = abits + ((size_t)b * PN + i0) * (PN / 32);

    const int vrow_l = ((lane >> 4) << 3) + (lane & 7);
    const int vcol_l = ((lane >> 3) & 1) << 3;

    constexpr int VR = NC / 32;
    uint4 vr[VR];
    uint2 er;
    uint32_t ar;
    const int l5 = tid & 31;
    const int pe = tid >> 3, pq = tid & 7;
    const size_t arow = (size_t)(tid >> 1) * (PN / 32) + (tid & 1);

#define PREFETCH_CHUNK(J0)                                                    \
    {                                                                         \
        _Pragma("unroll")                                                     \
        for (int r = 0; r < VR; r++) {                                        \
            int d = pe + 32 * r;                                              \
            vr[r] = *(const uint4*)(vbase + (size_t)d * PN + (J0) + pq * 8);  \
        }                                                                     \
        er.x = pp[(J0) / 2 + l5];                                             \
        er.y = mm[(J0) / 2 + l5];                                             \
        ar = abase[arow + ((J0) >> 5)];                                       \
    }

#define STORE_CHUNK(BUF)                                                      \
    {                                                                         \
        _Pragma("unroll")                                                     \
        for (int r = 0; r < VR; r++) {                                        \
            int d = pe + 32 * r;                                              \
            uint32_t off = d * 128 + pq * 16;                                 \
            uint32_t sw = off ^ ((off >> 3) & 0x70);                          \
            *(uint4*)(Vs[BUF] + sw) = vr[r];                                  \
        }                                                                     \
        if (tid < 32) es[BUF][tid] = er;                                      \
        aws[BUF][tid >> 1][tid & 1] = ar;                                     \
    }

    float acc[NC / 8][4];
#pragma unroll
    for (int nt = 0; nt < NC / 8; nt++)
#pragma unroll
        for (int u = 0; u < 4; u++) acc[nt][u] = 0.f;
    float rs0 = 0.f, rs1 = 0.f;

    PREFETCH_CHUNK(0);
    STORE_CHUNK(0);
    PREFETCH_CHUNK(64);
    __syncthreads();

    for (int c = 0; c < 32; c++) {
        const int buf = c & 1;
        if (c + 1 < 32) STORE_CHUNK(buf ^ 1);
        if (c + 2 < 32) PREFETCH_CHUNK((c + 2) * 64);

        const uint32_t sVs = smem_u32(Vs[buf]);
        const uint32_t aw00 = aws[buf][r0][0], aw01 = aws[buf][r0][1];
        const uint32_t aw10 = aws[buf][r1][0], aw11 = aws[buf][r1][1];

        __half2 h2s0 = __float2half2_rn(0.f);
        __half2 h2s1 = __float2half2_rn(0.f);

#pragma unroll
        for (int ks = 0; ks < 4; ks++) {
            const uint2 ea = es[buf][ks * 8 + (lane & 3)];
            const uint2 eb = es[buf][ks * 8 + (lane & 3) + 4];
            const uint32_t w0 = (ks < 2) ? aw00 : aw01;
            const uint32_t w1 = (ks < 2) ? aw10 : aw11;
            const int bb = (ks & 1) * 16 + cq;

            uint32_t a[4];
            a[0] = pmax2(E1p0, E1m0, ea.x, ea.y) & mask2(w0, bb);
            a[1] = pmax2(E1p1, E1m1, ea.x, ea.y) & mask2(w1, bb);
            a[2] = pmax2(E1p0, E1m0, eb.x, eb.y) & mask2(w0, bb + 8);
            a[3] = pmax2(E1p1, E1m1, eb.x, eb.y) & mask2(w1, bb + 8);

            h2s0 = __hadd2(h2s0, __hadd2(*(__half2*)&a[0], *(__half2*)&a[2]));
            h2s1 = __hadd2(h2s1, __hadd2(*(__half2*)&a[1], *(__half2*)&a[3]));

#pragma unroll
            for (int np = 0; np < NC / 16; np++) {
                int vrow = np * 16 + vrow_l;
                int vcol = ks * 16 + vcol_l;
                uint32_t off = vrow * 128 + vcol * 2;
                off ^= (off >> 3) & 0x70;
                uint32_t bH[4];
                ldsm_x4(bH, sVs + off);
                mma_f16(acc[2 * np],     a, bH);
                mma_f16(acc[2 * np + 1], a, bH + 2);
            }
        }
        {
            float2 f0 = __half22float2(h2s0);
            float2 f1 = __half22float2(h2s1);
            rs0 += f0.x + f0.y;
            rs1 += f1.x + f1.y;
        }
        __syncthreads();
    }
#undef PREFETCH_CHUNK
#undef STORE_CHUNK

    rs0 += __shfl_xor_sync(0xffffffffu, rs0, 1);
    rs0 += __shfl_xor_sync(0xffffffffu, rs0, 2);
    rs1 += __shfl_xor_sync(0xffffffffu, rs1, 1);
    rs1 += __shfl_xor_sync(0xffffffffu, rs1, 2);
    float inv0 = rs0 > 0.f ? 1.f / rs0 : 0.f;
    float inv1 = rs1 > 0.f ? 1.f / rs1 : 0.f;

    float accE[NC / 8][4];
#pragma unroll
    for (int nt = 0; nt < NC / 8; nt++) {
        accE[nt][0] = eluf(acc[nt][0] * inv0);
        accE[nt][1] = eluf(acc[nt][1] * inv0);
        accE[nt][2] = eluf(acc[nt][2] * inv1);
        accE[nt][3] = eluf(acc[nt][3] * inv1);
    }

    if constexpr (FUSE) {
        float accW[4][4];
#pragma unroll
        for (int nt = 0; nt < 4; nt++)
#pragma unroll
            for (int u = 0; u < 4; u++) accW[nt][u] = 0.f;

#pragma unroll
        for (int kt = 0; kt < 4; kt++) {
            uint32_t aH[4], aL[4];
            split2h(accE[2 * kt][0],     accE[2 * kt][1],     aH[0], aL[0]);
            split2h(accE[2 * kt][2],     accE[2 * kt][3],     aH[1], aL[1]);
            split2h(accE[2 * kt + 1][0], accE[2 * kt + 1][1], aH[2], aL[2]);
            split2h(accE[2 * kt + 1][2], accE[2 * kt + 1][3], aH[3], aL[3]);
            int k0 = kt * 16 + cq;
#pragma unroll
            for (int nt = 0; nt < 4; nt++) {
                int n = nt * 8 + (lane >> 2);
                uint32_t bH[2], bL[2];
                bH[0] = *(const uint32_t*)&WoH_s[n * PD + k0];
                bH[1] = *(const uint32_t*)&WoH_s[n * PD + k0 + 8];
                bL[0] = *(const uint32_t*)&WoL_s[n * PD + k0];
                bL[1] = *(const uint32_t*)&WoL_s[n * PD + k0 + 8];
                mma_f16(accW[nt], aH, bH);
                mma_f16(accW[nt], aH, bL);
                mma_f16(accW[nt], aL, bH);
            }
        }
        __half* w0 = Wp + ((size_t)h * PB * PN + (size_t)b * PN + i0 + r0) * PC;
        __half* w1 = Wp + ((size_t)h * PB * PN + (size_t)b * PN + i0 + r1) * PC;
#pragma unroll
        for (int nt = 0; nt < 4; nt++) {
            *(uint32_t*)(w0 + nt * 8 + cq) = pack2h(accW[nt][0], accW[nt][1]);
            *(uint32_t*)(w1 + nt * 8 + cq) = pack2h(accW[nt][2], accW[nt][3]);
        }
    } else {
        float* o0 = out + ((size_t)b * PN + i0 + r0) * PC;
        float* o1 = out + ((size_t)b * PN + i0 + r1) * PC;
#pragma unroll
        for (int nt = 0; nt < NC / 8; nt++) {
            int col = nt * 8 + cq;
            *(float2*)(o0 + col) = make_float2(accE[nt][0], accE[nt][1]);
            *(float2*)(o1 + col) = make_float2(accE[nt][2], accE[nt][3]);
        }
    }
}

// ---------------------------------------------------------------------------
// Kernel 4: combine fp16 per-head partials -> Wh2 row; exps; transposed V2
// ---------------------------------------------------------------------------
__global__ void comb_kernel(const __half* __restrict__ Wp,
                            const float* __restrict__ ao1,
                            const float* __restrict__ ao2,
                            __half* __restrict__ Vt2,
                            __half* __restrict__ e1p, __half* __restrict__ e1m,
                            __half* __restrict__ e2p, __half* __restrict__ e2m)
{
    int wrp = blockIdx.x * 8 + (threadIdx.x >> 5);
    int lane = threadIdx.x & 31;
    const size_t S = (size_t)PB * PN * PC;
    size_t o = (size_t)wrp * PC + lane;
    float v = __half2float(Wp[o]) + __half2float(Wp[S + o])
            + __half2float(Wp[2 * S + o]) + __half2float(Wp[3 * S + o]);

    int b = wrp >> 11;
    int n = wrp & (PN - 1);
    Vt2[((size_t)b * PC + lane) * PN + n] = __float2half_rn(v);

    float s1 = v * ao1[lane], s2 = v * ao2[lane];
#pragma unroll
    for (int of = 16; of; of >>= 1) {
        s1 += __shfl_xor_sync(0xffffffffu, s1, of);
        s2 += __shfl_xor_sync(0xffffffffu, s2, of);
    }
    if (lane == 0) {
        e1p[wrp] = __float2half(__expf(s1));
        e1m[wrp] = __float2half(__expf(0.2f * s1));
        e2p[wrp] = __float2half(__expf(s2));
        e2m[wrp] = __float2half(__expf(0.2f * s2));
    }
}

// ---------------------------------------------------------------------------
// Kernel 5: gather + Linear(32,32) + PReLU + Linear(32,2)
// ---------------------------------------------------------------------------
__global__ void cls_kernel(const float* __restrict__ h2,
                           const int*   __restrict__ idcs,
                           const float* __restrict__ W1,
                           const float* __restrict__ b1,
                           const float* __restrict__ pw,
                           const float* __restrict__ W2,
                           const float* __restrict__ b2,
                           float* __restrict__ out)
{
    int wrp = blockIdx.x * (blockDim.x >> 5) + (threadIdx.x >> 5);
    int lane = threadIdx.x & 31;
    if (wrp >= PB * PK1) return;
    int b = wrp >> 8;
    int idx = idcs[wrp];
    const float* ef = h2 + ((size_t)b * PN + idx) * PC;

    float y = b1[lane];
#pragma unroll
    for (int d = 0; d < PC; d++) y += ef[d] * W1[d * PC + lane];
    y = y > 0.f ? y : pw[lane] * y;

    float o0 = y * W2[lane * 2 + 0];
    float o1 = y * W2[lane * 2 + 1];
#pragma unroll
    for (int o = 16; o; o >>= 1) {
        o0 += __shfl_xor_sync(0xffffffffu, o0, o);
        o1 += __shfl_xor_sync(0xffffffffu, o1, o);
    }
    if (lane == 0) {
        out[wrp * 2 + 0] = o0 + b2[0];
        out[wrp * 2 + 1] = o1 + b2[1];
    }
}

// ---------------------------------------------------------------------------
extern "C" void kernel_launch(void* const* d_in, const int* in_sizes, int n_in,
                              void* d_out, int out_size)
{
    const float* x    = (const float*)d_in[0];
    const int*   adj  = (const int*)  d_in[1];
    const int*   idcs = (const int*)  d_in[2];
    const float* W    = (const float*)d_in[3];
    const float* a1   = (const float*)d_in[4];
    const float* a2   = (const float*)d_in[5];
    const float* Wo   = (const float*)d_in[6];
    const float* ao1  = (const float*)d_in[7];
    const float* ao2  = (const float*)d_in[8];
    const float* W1   = (const float*)d_in[9];
    const float* b1   = (const float*)d_in[10];
    const float* pw   = (const float*)d_in[11];
    const float* W2   = (const float*)d_in[12];
    const float* b2   = (const float*)d_in[13];
    float* out = (float*)d_out;

    float* p_h2;
    __half *p_wp, *p_vh, *p_xh, *p_xl, *p_e1p, *p_e1m, *p_e2p, *p_e2m;
    uint32_t* p_ab;
    cudaGetSymbolAddress((void**)&p_h2,  g_h2);
    cudaGetSymbolAddress((void**)&p_wp,  g_W2p);
    cudaGetSymbolAddress((void**)&p_ab,  g_abits);
    cudaGetSymbolAddress((void**)&p_vh,  g_VtH);
    cudaGetSymbolAddress((void**)&p_xh,  g_xH);
    cudaGetSymbolAddress((void**)&p_xl,  g_xL);
    cudaGetSymbolAddress((void**)&p_e1p, g_e1p);
    cudaGetSymbolAddress((void**)&p_e1m, g_e1m);
    cudaGetSymbolAddress((void**)&p_e2p, g_e2p);
    cudaGetSymbolAddress((void**)&p_e2m, g_e2m);

    cudaFuncSetAttribute(gemm1_mma_kernel,
                         cudaFuncAttributeMaxDynamicSharedMemorySize, SM1_TOTAL);

    xsplit_kernel<<<(PB * PN * PF) / 4 / 256, 256>>>(x, p_xh, p_xl);
    adjbits_kernel<<<(PB * PN * PN) / 256, 256>>>(adj, p_ab);

    gemm1_mma_kernel<<<dim3(PN / 128, PB * PH), 256, SM1_TOTAL>>>(
        p_xh, p_xl, W, a1, a2, p_vh, p_e1p, p_e1m, p_e2p, p_e2m);

    attn_mma_kernel<PD, true><<<dim3(PN / 128, PB * PH), 256>>>(
        p_e1p, p_e1m, p_e2p, p_e2m, p_vh, p_ab, Wo, p_wp, nullptr, 2);

    comb_kernel<<<PB * PN / 8, 256>>>(p_wp, ao1, ao2, p_vh,
                                      p_e1p, p_e1m, p_e2p, p_e2m);

    attn_mma_kernel<PC, false><<<dim3(PN / 128, PB), 256>>>(
        p_e1p, p_e1m, p_e2p, p_e2m, p_vh, p_ab, nullptr, nullptr, p_h2, 0);

    cls_kernel<<<(PB * PK1) / 8, 256>>>(p_h2, idcs, W1, b1, pw, W2, b2, out);
}

// round 16
// speedup vs baseline: 1.1165x; 1.0233x over previous
#include <cuda_runtime.h>
#include <cuda_fp16.h>
#include <math.h>
#include <stdint.h>

// Problem constants
#define PB 4
#define PN 2048
#define PF 256
#define PD 64      // NHID
#define PH 4       // NHEADS
#define PC 32      // NCLASS
#define PK1 256

// ---------------- scratch (device globals, no allocation) ----------------
__device__ float g_h2[PB * PN * PC];
__device__ __half g_W2p[PH * PB * PN * PC];        // per-head gemm2 partials, 8 MB
__device__ uint32_t g_abits[PB * PN * (PN / 32)];  // adjacency bitmask
__device__ __half g_VtH[PB * PH * PD * PN];        // [g][d][n] fp16 (reused by layer 2)
__device__ __half g_xH[PB * PN * PF];              // x split hi, 4 MB
__device__ __half g_xL[PB * PN * PF];              // x split lo, 4 MB
__device__ __half g_e1p[PB * PH * PN];             // factored exps, fp16
__device__ __half g_e1m[PB * PH * PN];
__device__ __half g_e2p[PB * PH * PN];
__device__ __half g_e2m[PB * PH * PN];

// =========================== helpers ===================================
__device__ __forceinline__ uint32_t smem_u32(const void* p) {
    uint32_t a;
    asm("{ .reg .u64 t; cvta.to.shared.u64 t, %1; cvt.u32.u64 %0, t; }"
        : "=r"(a) : "l"(p));
    return a;
}
// pack2h(lo, hi): f16x2 with lo in bits[0:16)
__device__ __forceinline__ uint32_t pack2h(float lo, float hi) {
    uint32_t r;
    asm("cvt.rn.f16x2.f32 %0, %1, %2;" : "=r"(r) : "f"(hi), "f"(lo));
    return r;
}
// split pair into fp16 hi + fp16 residual (packed)
__device__ __forceinline__ void split2h(float x, float y, uint32_t& hi, uint32_t& lo) {
    hi = pack2h(x, y);
    __half2 hh = *(__half2*)&hi;
    lo = pack2h(x - __low2float(hh), y - __high2float(hh));
}
__device__ __forceinline__ void mma_f16(float* d, const uint32_t* a, const uint32_t* b) {
    asm volatile(
        "mma.sync.aligned.m16n8k16.row.col.f32.f16.f16.f32 "
        "{%0,%1,%2,%3}, {%4,%5,%6,%7}, {%8,%9}, {%0,%1,%2,%3};"
        : "+f"(d[0]), "+f"(d[1]), "+f"(d[2]), "+f"(d[3])
        : "r"(a[0]), "r"(a[1]), "r"(a[2]), "r"(a[3]), "r"(b[0]), "r"(b[1]));
}
__device__ __forceinline__ void ldsm_x4(uint32_t* r, uint32_t addr) {
    asm volatile("ldmatrix.sync.aligned.m8n8.x4.shared.b16 {%0,%1,%2,%3}, [%4];"
                 : "=r"(r[0]), "=r"(r[1]), "=r"(r[2]), "=r"(r[3]) : "r"(addr));
}
// 2-bit -> per-half mask32 (bits isolated FIRST — R9 lesson)
__device__ __forceinline__ uint32_t mask2(uint32_t w, int bb) {
    uint32_t y = (w >> bb) & 3u;
    return ((y | (y << 15)) & 0x00010001u) * 0xFFFFu;
}
// p = max(e1p*e2p, e1m*e2m) packed fp16x2 (== exp(leakyrelu(f1+f2)))
__device__ __forceinline__ uint32_t pmax2(__half2 e1p, __half2 e1m,
                                          uint32_t e2p, uint32_t e2m) {
    __half2 a = __hmul2(e1p, *(__half2*)&e2p);
    __half2 b = __hmul2(e1m, *(__half2*)&e2m);
    __half2 m = __hmax2(a, b);
    return *(uint32_t*)&m;
}
__device__ __forceinline__ float eluf(float v) {
    return v > 0.f ? v : expm1f(v);
}

// ---------------------------------------------------------------------------
// Kernel 0: split x fp32 -> fp16 hi/lo
// ---------------------------------------------------------------------------
__global__ void xsplit_kernel(const float* __restrict__ x,
                              __half* __restrict__ xH, __half* __restrict__ xL)
{
    int t = (blockIdx.x * 256 + threadIdx.x) * 4;
    float4 v = *(const float4*)(x + t);
    uint32_t h0, l0, h1, l1;
    split2h(v.x, v.y, h0, l0);
    split2h(v.z, v.w, h1, l1);
    *(uint2*)(xH + t) = make_uint2(h0, h1);
    *(uint2*)(xL + t) = make_uint2(l0, l1);
}

// ---------------------------------------------------------------------------
// Kernel 1: tensor-core gemm1 (R14, passing): Wh1 = x @ W[h], fused epilogue
// ---------------------------------------------------------------------------
#define WS_STRIDE 264
#define SM1_TOTAL (67584 + 512)

__global__ void __launch_bounds__(256) gemm1_mma_kernel(
    const __half* __restrict__ xH, const __half* __restrict__ xL,
    const float* __restrict__ W,
    const float* __restrict__ a1, const float* __restrict__ a2,
    __half* __restrict__ VtH,
    __half* __restrict__ e1p, __half* __restrict__ e1m,
    __half* __restrict__ e2p, __half* __restrict__ e2m)
{
    extern __shared__ char sm1[];
    __half* WsH = (__half*)sm1;                    // [64][WS_STRIDE]
    __half* WsL = (__half*)(sm1 + 33792);
    float* a1s = (float*)(sm1 + 67584);            // [64]
    float* a2s = a1s + 64;

    const int it = blockIdx.x;
    const int bh = blockIdx.y;
    const int b  = bh >> 2;
    const int h  = bh & 3;
    const int i0 = it * 128;
    const int tid = threadIdx.x;
    const int lane = tid & 31, wid = tid >> 5;

    {
        const float* Wh = W + (size_t)h * PF * PD;
        for (int e = tid; e < PF * PD; e += 256) {
            int d = e & 63, f = e >> 6;
            float v = Wh[(size_t)f * PD + d];
            __half hv = __float2half_rn(v);
            WsH[d * WS_STRIDE + f] = hv;
            WsL[d * WS_STRIDE + f] = __float2half_rn(v - __half2float(hv));
        }
        if (tid < 64) { a1s[tid] = a1[h * PD + tid]; a2s[tid] = a2[h * PD + tid]; }
    }
    __syncthreads();

    const int r0 = wid * 16 + (lane >> 2);
    const int r1 = r0 + 8;
    const int cq = (lane & 3) * 2;
    const __half* xr0H = xH + ((size_t)b * PN + i0 + r0) * PF;
    const __half* xr1H = xH + ((size_t)b * PN + i0 + r1) * PF;
    const __half* xr0L = xL + ((size_t)b * PN + i0 + r0) * PF;
    const __half* xr1L = xL + ((size_t)b * PN + i0 + r1) * PF;

    float acc[8][4];
#pragma unroll
    for (int nt = 0; nt < 8; nt++)
#pragma unroll
        for (int u = 0; u < 4; u++) acc[nt][u] = 0.f;

#pragma unroll 4
    for (int ks = 0; ks < 16; ks++) {
        const int k0 = ks * 16 + cq;
        uint32_t aH[4], aL[4];
        aH[0] = *(const uint32_t*)(xr0H + k0);
        aH[1] = *(const uint32_t*)(xr1H + k0);
        aH[2] = *(const uint32_t*)(xr0H + k0 + 8);
        aH[3] = *(const uint32_t*)(xr1H + k0 + 8);
        aL[0] = *(const uint32_t*)(xr0L + k0);
        aL[1] = *(const uint32_t*)(xr1L + k0);
        aL[2] = *(const uint32_t*)(xr0L + k0 + 8);
        aL[3] = *(const uint32_t*)(xr1L + k0 + 8);
#pragma unroll
        for (int nt = 0; nt < 8; nt++) {
            int n = nt * 8 + (lane >> 2);
            uint32_t bH[2], bL[2];
            bH[0] = *(const uint32_t*)&WsH[n * WS_STRIDE + k0];
            bH[1] = *(const uint32_t*)&WsH[n * WS_STRIDE + k0 + 8];
            bL[0] = *(const uint32_t*)&WsL[n * WS_STRIDE + k0];
            bL[1] = *(const uint32_t*)&WsL[n * WS_STRIDE + k0 + 8];
            mma_f16(acc[nt], aH, bH);
            mma_f16(acc[nt], aH, bL);
            mma_f16(acc[nt], aL, bH);
        }
    }

    // f1/f2 dots via quad shuffles, then exps
    {
        float p10 = 0.f, p20 = 0.f, p11 = 0.f, p21 = 0.f;
#pragma unroll
        for (int nt = 0; nt < 8; nt++) {
            float w1a = a1s[nt * 8 + cq], w1b = a1s[nt * 8 + cq + 1];
            float w2a = a2s[nt * 8 + cq], w2b = a2s[nt * 8 + cq + 1];
            p10 += acc[nt][0] * w1a + acc[nt][1] * w1b;
            p20 += acc[nt][0] * w2a + acc[nt][1] * w2b;
            p11 += acc[nt][2] * w1a + acc[nt][3] * w1b;
            p21 += acc[nt][2] * w2a + acc[nt][3] * w2b;
        }
        p10 += __shfl_xor_sync(0xffffffffu, p10, 1);
        p10 += __shfl_xor_sync(0xffffffffu, p10, 2);
        p20 += __shfl_xor_sync(0xffffffffu, p20, 1);
        p20 += __shfl_xor_sync(0xffffffffu, p20, 2);
        p11 += __shfl_xor_sync(0xffffffffu, p11, 1);
        p11 += __shfl_xor_sync(0xffffffffu, p11, 2);
        p21 += __shfl_xor_sync(0xffffffffu, p21, 1);
        p21 += __shfl_xor_sync(0xffffffffu, p21, 2);
        if ((lane & 3) == 0) {
            size_t o0 = (size_t)bh * PN + i0 + r0;
            size_t o1 = (size_t)bh * PN + i0 + r1;
            e1p[o0] = __float2half(__expf(p10));
            e1m[o0] = __float2half(__expf(0.2f * p10));
            e2p[o0] = __float2half(__expf(p20));
            e2m[o0] = __float2half(__expf(0.2f * p20));
            e1p[o1] = __float2half(__expf(p11));
            e1m[o1] = __float2half(__expf(0.2f * p11));
            e2p[o1] = __float2half(__expf(p21));
            e2m[o1] = __float2half(__expf(0.2f * p21));
        }
    }

    // transposed fp16 V via smem (overlay on Ws)
    __syncthreads();
    __half* Ts = (__half*)sm1;   // [128][72]
#pragma unroll
    for (int nt = 0; nt < 8; nt++) {
        *(uint32_t*)&Ts[r0 * 72 + nt * 8 + cq] = pack2h(acc[nt][0], acc[nt][1]);
        *(uint32_t*)&Ts[r1 * 72 + nt * 8 + cq] = pack2h(acc[nt][2], acc[nt][3]);
    }
    __syncthreads();
    {
        int d = tid >> 2, ng = tid & 3;
        __half* dst = VtH + ((size_t)bh * PD + d) * PN + i0 + ng * 32;
#pragma unroll
        for (int m = 0; m < 8; m++) {
            int n = ng * 32 + m * 4;
            uint2 v;
            v.x = pack2h(__half2float(Ts[n * 72 + d]),
                         __half2float(Ts[(n + 1) * 72 + d]));
            v.y = pack2h(__half2float(Ts[(n + 2) * 72 + d]),
                         __half2float(Ts[(n + 3) * 72 + d]));
            *(uint2*)(dst + m * 4) = v;
        }
    }
}

// ---------------------------------------------------------------------------
// Kernel 2: pack adj>0 into bitmask
// ---------------------------------------------------------------------------
__global__ void adjbits_kernel(const int* __restrict__ adj,
                               uint32_t* __restrict__ bits)
{
    size_t t = (size_t)blockIdx.x * 256 + threadIdx.x;
    int a = adj[t];
    unsigned m = __ballot_sync(0xffffffffu, a > 0);
    if ((threadIdx.x & 31) == 0) bits[t >> 5] = m;
}

// ---------------------------------------------------------------------------
// Kernel 3: warp-MMA attention, double-buffered, HADD2 rowsums.
//   Templated NW: NW warps x 16 rows = NW*16 rows/block.
//   attn1: NW=8 (unchanged). attn2: NW=4, grid 2x -> 2x SM parallelism.
// ---------------------------------------------------------------------------
template<int NC, bool FUSE, int NW>
__global__ void __launch_bounds__(NW * 32) attn_mma_kernel(
    const __half* __restrict__ e1pg, const __half* __restrict__ e1mg,
    const __half* __restrict__ e2pg, const __half* __restrict__ e2mg,
    const __half* __restrict__ Vt, const uint32_t* __restrict__ abits,
    const float* __restrict__ Wo, __half* __restrict__ Wp,
    float* __restrict__ out, int hshift)
{
    constexpr int NT = NW * 32;        // threads
    constexpr int ROWS = NW * 16;      // i-rows per block
    __shared__ __align__(128) char Vs[2][NC * 128];
    __shared__ uint2 es[2][32];
    __shared__ uint32_t aws[2][ROWS][2];
    __shared__ __align__(4) __half WoH_s[FUSE ? PD * PC : 2];
    __shared__ __align__(4) __half WoL_s[FUSE ? PD * PC : 2];

    const int tid = threadIdx.x;
    const int lane = tid & 31, wid = tid >> 5;
    const int g = blockIdx.y;
    const int b = g >> hshift;
    const int h = g & ((1 << hshift) - 1);
    const int i0 = blockIdx.x * ROWS;

    const int r0 = wid * 16 + (lane >> 2);
    const int r1 = r0 + 8;
    const int cq = (lane & 3) * 2;

    if constexpr (FUSE) {
        const float* Woh = Wo + (size_t)h * PD * PC;
        for (int e = tid; e < PD * PC; e += NT) {
            int k = e >> 5, n = e & 31;
            float v = Woh[k * PC + n];
            __half hv = __float2half_rn(v);
            WoH_s[n * PD + k] = hv;
            WoL_s[n * PD + k] = __float2half_rn(v - __half2float(hv));
        }
    }

    const __half2 E1p0 = __half2half2(e1pg[(size_t)g * PN + i0 + r0]);
    const __half2 E1m0 = __half2half2(e1mg[(size_t)g * PN + i0 + r0]);
    const __half2 E1p1 = __half2half2(e1pg[(size_t)g * PN + i0 + r1]);
    const __half2 E1m1 = __half2half2(e1mg[(size_t)g * PN + i0 + r1]);

    const uint32_t* pp = (const uint32_t*)(e2pg + (size_t)g * PN);
    const uint32_t* mm = (const uint32_t*)(e2mg + (size_t)g * PN);
    const __half* vbase = Vt + (size_t)g * NC * PN;
    const uint32_t* abase = abits + ((size_t)b * PN + i0) * (PN / 32);

    const int vrow_l = ((lane >> 4) << 3) + (lane & 7);
    const int vcol_l = ((lane >> 3) & 1) << 3;

    constexpr int VR = NC * 8 / NT;    // uint4 staging elems per thread
    uint4 vr[VR];
    uint2 er;
    uint32_t ar;
    const int l5 = tid & 31;
    const int pe = tid >> 3, pq = tid & 7;
    const size_t arow = (size_t)(tid >> 1) * (PN / 32) + (tid & 1);

#define PREFETCH_CHUNK(J0)                                                     \
    {                                                                          \
        _Pragma("unroll")                                                      \
        for (int r = 0; r < VR; r++) {                                         \
            int d = pe + (NT / 8) * r;                                         \
            vr[r] = *(const uint4*)(vbase + (size_t)d * PN + (J0) + pq * 8);   \
        }                                                                      \
        er.x = pp[(J0) / 2 + l5];                                              \
        er.y = mm[(J0) / 2 + l5];                                              \
        ar = abase[arow + ((J0) >> 5)];                                        \
    }

#define STORE_CHUNK(BUF)                                                       \
    {                                                                          \
        _Pragma("unroll")                                                      \
        for (int r = 0; r < VR; r++) {                                         \
            int d = pe + (NT / 8) * r;                                         \
            uint32_t off = d * 128 + pq * 16;                                  \
            uint32_t sw = off ^ ((off >> 3) & 0x70);                           \
            *(uint4*)(Vs[BUF] + sw) = vr[r];                                   \
        }                                                                      \
        if (tid < 32) es[BUF][tid] = er;                                       \
        aws[BUF][tid >> 1][tid & 1] = ar;                                      \
    }

    float acc[NC / 8][4];
#pragma unroll
    for (int nt = 0; nt < NC / 8; nt++)
#pragma unroll
        for (int u = 0; u < 4; u++) acc[nt][u] = 0.f;
    float rs0 = 0.f, rs1 = 0.f;

    PREFETCH_CHUNK(0);
    STORE_CHUNK(0);
    PREFETCH_CHUNK(64);
    __syncthreads();

    for (int c = 0; c < 32; c++) {
        const int buf = c & 1;
        if (c + 1 < 32) STORE_CHUNK(buf ^ 1);
        if (c + 2 < 32) PREFETCH_CHUNK((c + 2) * 64);

        const uint32_t sVs = smem_u32(Vs[buf]);
        const uint32_t aw00 = aws[buf][r0][0], aw01 = aws[buf][r0][1];
        const uint32_t aw10 = aws[buf][r1][0], aw11 = aws[buf][r1][1];

        __half2 h2s0 = __float2half2_rn(0.f);
        __half2 h2s1 = __float2half2_rn(0.f);

#pragma unroll
        for (int ks = 0; ks < 4; ks++) {
            const uint2 ea = es[buf][ks * 8 + (lane & 3)];
            const uint2 eb = es[buf][ks * 8 + (lane & 3) + 4];
            const uint32_t w0 = (ks < 2) ? aw00 : aw01;
            const uint32_t w1 = (ks < 2) ? aw10 : aw11;
            const int bb = (ks & 1) * 16 + cq;

            uint32_t a[4];
            a[0] = pmax2(E1p0, E1m0, ea.x, ea.y) & mask2(w0, bb);
            a[1] = pmax2(E1p1, E1m1, ea.x, ea.y) & mask2(w1, bb);
            a[2] = pmax2(E1p0, E1m0, eb.x, eb.y) & mask2(w0, bb + 8);
            a[3] = pmax2(E1p1, E1m1, eb.x, eb.y) & mask2(w1, bb + 8);

            h2s0 = __hadd2(h2s0, __hadd2(*(__half2*)&a[0], *(__half2*)&a[2]));
            h2s1 = __hadd2(h2s1, __hadd2(*(__half2*)&a[1], *(__half2*)&a[3]));

#pragma unroll
            for (int np = 0; np < NC / 16; np++) {
                int vrow = np * 16 + vrow_l;
                int vcol = ks * 16 + vcol_l;
                uint32_t off = vrow * 128 + vcol * 2;
                off ^= (off >> 3) & 0x70;
                uint32_t bH[4];
                ldsm_x4(bH, sVs + off);
                mma_f16(acc[2 * np],     a, bH);
                mma_f16(acc[2 * np + 1], a, bH + 2);
            }
        }
        {
            float2 f0 = __half22float2(h2s0);
            float2 f1 = __half22float2(h2s1);
            rs0 += f0.x + f0.y;
            rs1 += f1.x + f1.y;
        }
        __syncthreads();
    }
#undef PREFETCH_CHUNK
#undef STORE_CHUNK

    rs0 += __shfl_xor_sync(0xffffffffu, rs0, 1);
    rs0 += __shfl_xor_sync(0xffffffffu, rs0, 2);
    rs1 += __shfl_xor_sync(0xffffffffu, rs1, 1);
    rs1 += __shfl_xor_sync(0xffffffffu, rs1, 2);
    float inv0 = rs0 > 0.f ? 1.f / rs0 : 0.f;
    float inv1 = rs1 > 0.f ? 1.f / rs1 : 0.f;

    float accE[NC / 8][4];
#pragma unroll
    for (int nt = 0; nt < NC / 8; nt++) {
        accE[nt][0] = eluf(acc[nt][0] * inv0);
        accE[nt][1] = eluf(acc[nt][1] * inv0);
        accE[nt][2] = eluf(acc[nt][2] * inv1);
        accE[nt][3] = eluf(acc[nt][3] * inv1);
    }

    if constexpr (FUSE) {
        float accW[4][4];
#pragma unroll
        for (int nt = 0; nt < 4; nt++)
#pragma unroll
            for (int u = 0; u < 4; u++) accW[nt][u] = 0.f;

#pragma unroll
        for (int kt = 0; kt < 4; kt++) {
            uint32_t aH[4], aL[4];
            split2h(accE[2 * kt][0],     accE[2 * kt][1],     aH[0], aL[0]);
            split2h(accE[2 * kt][2],     accE[2 * kt][3],     aH[1], aL[1]);
            split2h(accE[2 * kt + 1][0], accE[2 * kt + 1][1], aH[2], aL[2]);
            split2h(accE[2 * kt + 1][2], accE[2 * kt + 1][3], aH[3], aL[3]);
            int k0 = kt * 16 + cq;
#pragma unroll
            for (int nt = 0; nt < 4; nt++) {
                int n = nt * 8 + (lane >> 2);
                uint32_t bH[2], bL[2];
                bH[0] = *(const uint32_t*)&WoH_s[n * PD + k0];
                bH[1] = *(const uint32_t*)&WoH_s[n * PD + k0 + 8];
                bL[0] = *(const uint32_t*)&WoL_s[n * PD + k0];
                bL[1] = *(const uint32_t*)&WoL_s[n * PD + k0 + 8];
                mma_f16(accW[nt], aH, bH);
                mma_f16(accW[nt], aH, bL);
                mma_f16(accW[nt], aL, bH);
            }
        }
        __half* w0 = Wp + ((size_t)h * PB * PN + (size_t)b * PN + i0 + r0) * PC;
        __half* w1 = Wp + ((size_t)h * PB * PN + (size_t)b * PN + i0 + r1) * PC;
#pragma unroll
        for (int nt = 0; nt < 4; nt++) {
            *(uint32_t*)(w0 + nt * 8 + cq) = pack2h(accW[nt][0], accW[nt][1]);
            *(uint32_t*)(w1 + nt * 8 + cq) = pack2h(accW[nt][2], accW[nt][3]);
        }
    } else {
        float* o0 = out + ((size_t)b * PN + i0 + r0) * PC;
        float* o1 = out + ((size_t)b * PN + i0 + r1) * PC;
#pragma unroll
        for (int nt = 0; nt < NC / 8; nt++) {
            int col = nt * 8 + cq;
            *(float2*)(o0 + col) = make_float2(accE[nt][0], accE[nt][1]);
            *(float2*)(o1 + col) = make_float2(accE[nt][2], accE[nt][3]);
        }
    }
}

// ---------------------------------------------------------------------------
// Kernel 4: combine fp16 per-head partials -> Wh2 row; exps; transposed V2
// ---------------------------------------------------------------------------
__global__ void comb_kernel(const __half* __restrict__ Wp,
                            const float* __restrict__ ao1,
                            const float* __restrict__ ao2,
                            __half* __restrict__ Vt2,
                            __half* __restrict__ e1p, __half* __restrict__ e1m,
                            __half* __restrict__ e2p, __half* __restrict__ e2m)
{
    int wrp = blockIdx.x * 8 + (threadIdx.x >> 5);
    int lane = threadIdx.x & 31;
    const size_t S = (size_t)PB * PN * PC;
    size_t o = (size_t)wrp * PC + lane;
    float v = __half2float(Wp[o]) + __half2float(Wp[S + o])
            + __half2float(Wp[2 * S + o]) + __half2float(Wp[3 * S + o]);

    int b = wrp >> 11;
    int n = wrp & (PN - 1);
    Vt2[((size_t)b * PC + lane) * PN + n] = __float2half_rn(v);

    float s1 = v * ao1[lane], s2 = v * ao2[lane];
#pragma unroll
    for (int of = 16; of; of >>= 1) {
        s1 += __shfl_xor_sync(0xffffffffu, s1, of);
        s2 += __shfl_xor_sync(0xffffffffu, s2, of);
    }
    if (lane == 0) {
        e1p[wrp] = __float2half(__expf(s1));
        e1m[wrp] = __float2half(__expf(0.2f * s1));
        e2p[wrp] = __float2half(__expf(s2));
        e2m[wrp] = __float2half(__expf(0.2f * s2));
    }
}

// ---------------------------------------------------------------------------
// Kernel 5: gather + Linear(32,32) + PReLU + Linear(32,2)
// ---------------------------------------------------------------------------
__global__ void cls_kernel(const float* __restrict__ h2,
                           const int*   __restrict__ idcs,
                           const float* __restrict__ W1,
                           const float* __restrict__ b1,
                           const float* __restrict__ pw,
                           const float* __restrict__ W2,
                           const float* __restrict__ b2,
                           float* __restrict__ out)
{
    int wrp = blockIdx.x * (blockDim.x >> 5) + (threadIdx.x >> 5);
    int lane = threadIdx.x & 31;
    if (wrp >= PB * PK1) return;
    int b = wrp >> 8;
    int idx = idcs[wrp];
    const float* ef = h2 + ((size_t)b * PN + idx) * PC;

    float y = b1[lane];
#pragma unroll
    for (int d = 0; d < PC; d++) y += ef[d] * W1[d * PC + lane];
    y = y > 0.f ? y : pw[lane] * y;

    float o0 = y * W2[lane * 2 + 0];
    float o1 = y * W2[lane * 2 + 1];
#pragma unroll
    for (int o = 16; o; o >>= 1) {
        o0 += __shfl_xor_sync(0xffffffffu, o0, o);
        o1 += __shfl_xor_sync(0xffffffffu, o1, o);
    }
    if (lane == 0) {
        out[wrp * 2 + 0] = o0 + b2[0];
        out[wrp * 2 + 1] = o1 + b2[1];
    }
}

// ---------------------------------------------------------------------------
extern "C" void kernel_launch(void* const* d_in, const int* in_sizes, int n_in,
                              void* d_out, int out_size)
{
    const float* x    = (const float*)d_in[0];
    const int*   adj  = (const int*)  d_in[1];
    const int*   idcs = (const int*)  d_in[2];
    const float* W    = (const float*)d_in[3];
    const float* a1   = (const float*)d_in[4];
    const float* a2   = (const float*)d_in[5];
    const float* Wo   = (const float*)d_in[6];
    const float* ao1  = (const float*)d_in[7];
    const float* ao2  = (const float*)d_in[8];
    const float* W1   = (const float*)d_in[9];
    const float* b1   = (const float*)d_in[10];
    const float* pw   = (const float*)d_in[11];
    const float* W2   = (const float*)d_in[12];
    const float* b2   = (const float*)d_in[13];
    float* out = (float*)d_out;

    float* p_h2;
    __half *p_wp, *p_vh, *p_xh, *p_xl, *p_e1p, *p_e1m, *p_e2p, *p_e2m;
    uint32_t* p_ab;
    cudaGetSymbolAddress((void**)&p_h2,  g_h2);
    cudaGetSymbolAddress((void**)&p_wp,  g_W2p);
    cudaGetSymbolAddress((void**)&p_ab,  g_abits);
    cudaGetSymbolAddress((void**)&p_vh,  g_VtH);
    cudaGetSymbolAddress((void**)&p_xh,  g_xH);
    cudaGetSymbolAddress((void**)&p_xl,  g_xL);
    cudaGetSymbolAddress((void**)&p_e1p, g_e1p);
    cudaGetSymbolAddress((void**)&p_e1m, g_e1m);
    cudaGetSymbolAddress((void**)&p_e2p, g_e2p);
    cudaGetSymbolAddress((void**)&p_e2m, g_e2m);

    cudaFuncSetAttribute(gemm1_mma_kernel,
                         cudaFuncAttributeMaxDynamicSharedMemorySize, SM1_TOTAL);

    xsplit_kernel<<<(PB * PN * PF) / 4 / 256, 256>>>(x, p_xh, p_xl);
    adjbits_kernel<<<(PB * PN * PN) / 256, 256>>>(adj, p_ab);

    gemm1_mma_kernel<<<dim3(PN / 128, PB * PH), 256, SM1_TOTAL>>>(
        p_xh, p_xl, W, a1, a2, p_vh, p_e1p, p_e1m, p_e2p, p_e2m);

    attn_mma_kernel<PD, true, 8><<<dim3(PN / 128, PB * PH), 256>>>(
        p_e1p, p_e1m, p_e2p, p_e2m, p_vh, p_ab, Wo, p_wp, nullptr, 2);

    comb_kernel<<<PB * PN / 8, 256>>>(p_wp, ao1, ao2, p_vh,
                                      p_e1p, p_e1m, p_e2p, p_e2m);

    attn_mma_kernel<PC, false, 4><<<dim3(PN / 64, PB), 128>>>(
        p_e1p, p_e1m, p_e2p, p_e2m, p_vh, p_ab, nullptr, nullptr, p_h2, 0);

    cls_kernel<<<(PB * PK1) / 8, 256>>>(p_h2, idcs, W1, b1, pw, W2, b2, out);
}